// round 12
// baseline (speedup 1.0000x reference)
#include <cuda_runtime.h>
#include <cuda_fp16.h>

#define NN   100000
#define EE   1600000
#define CIN  1024
#define HD   64
#define ZDIM 32

#define NBLK ((NN + 255) / 256)   // 391

// ---------------- scratch (static __device__ — no allocation) ----------------
__device__ int   g_is64;
__device__ int   g_total;
__device__ int   g_deg[NN];
__device__ int   g_off[NN];
__device__ int   g_cur[NN];
__device__ int   g_csr[EE];
__device__ float g_dinv[NN];
__device__ unsigned g_t1h[NN * 32 + 32];  // dinv-scaled x@Wg1, fp16 half2 (+zero pad row)
__device__ unsigned g_t2h[NN * 16 + 16];  // dinv-scaled encoder z, fp16 half2 (+zero pad row)
__device__ unsigned g_dzp[NN * 32];       // decoder hidden, fp16 half2 words

// fp16 frag-packed weights
__device__ __align__(16) unsigned g_Wg1p[64 * 8 * 64];     // 128 KB
__device__ __align__(16) unsigned g_Wf2p[4 * 128 * 64];    // 128 KB

// ---------------- helpers ----------------
__device__ __forceinline__ unsigned h2pack(float x0, float x1) {
    __half2 h = __float22half2_rn(make_float2(x0, x1));
    return *reinterpret_cast<unsigned*>(&h);
}
__device__ __forceinline__ float2 h2unpack(unsigned w) {
    return __half22float2(*reinterpret_cast<__half2*>(&w));
}

__device__ __forceinline__ void mma16816h(float* c, const unsigned* a, unsigned b0, unsigned b1) {
    asm volatile(
        "mma.sync.aligned.m16n8k16.row.col.f32.f16.f16.f32 "
        "{%0,%1,%2,%3}, {%4,%5,%6,%7}, {%8,%9}, {%0,%1,%2,%3};\n"
        : "+f"(c[0]), "+f"(c[1]), "+f"(c[2]), "+f"(c[3])
        : "r"(a[0]), "r"(a[1]), "r"(a[2]), "r"(a[3]), "r"(b0), "r"(b1));
}

__device__ __forceinline__ void cp16(unsigned smem_addr, const void* gptr) {
    asm volatile("cp.async.ca.shared.global [%0], [%1], 16;\n"
                 :: "r"(smem_addr), "l"(gptr));
}
__device__ __forceinline__ void cp_commit() { asm volatile("cp.async.commit_group;\n"); }
__device__ __forceinline__ void cp_wait1()  { asm volatile("cp.async.wait_group 1;\n" ::: "memory"); }

// ---------------- weight pack helper (device) ----------------
__device__ __forceinline__ void pack_one(const float* __restrict__ W, int K, int N,
                                         unsigned* __restrict__ pw, int idx) {
    int lane2 = idx & 63;
    int j = lane2 & 1;
    int lane = lane2 >> 1;
    int nb = (idx >> 6) % (N / 8);
    int kc = idx / (64 * (N / 8));
    int k0 = kc * 16 + (lane & 3) * 2 + j * 8;
    int n = nb * 8 + (lane >> 2);
    pw[idx] = h2pack(W[(long long)k0 * N + n], W[(long long)(k0 + 1) * N + n]);
}

// ---------------- prep ----------------
__global__ void prep_kernel(const int* __restrict__ ei32,
                            const float* __restrict__ Wg1,
                            const float* __restrict__ Wf2) {
    int i = blockIdx.x * blockDim.x + threadIdx.x;
    if (i < NN) g_deg[i] = 0;
    if (i < 32) g_t1h[NN * 32 + i] = 0;
    if (i < 16) g_t2h[NN * 16 + i] = 0;
    if (i == 0) {
        int nz = 0;
        for (int k = 0; k < 64; k++) nz |= (ei32[2 * k + 1] != 0);
        g_is64 = nz ? 0 : 1;
        g_total = 0;
    }
    if (i < 64 * 8 * 64) {
        pack_one(Wg1, CIN, HD, g_Wg1p, i);
        pack_one(Wf2, HD, CIN, g_Wf2p, i);
    }
}

__global__ void hist_kernel(const void* __restrict__ ei) {
    int is64 = g_is64;
    int e = blockIdx.x * blockDim.x + threadIdx.x;
    if (e < EE) {
        int d = is64 ? (int)((const long long*)ei)[EE + e]
                     : ((const int*)ei)[EE + e];
        atomicAdd(&g_deg[d], 1);
    }
}

__global__ void alloc_kernel() {
    int i = blockIdx.x * blockDim.x + threadIdx.x;
    int lane = threadIdx.x & 31;
    int d = (i < NN) ? g_deg[i] : 0;
    int p = d;
#pragma unroll
    for (int o = 1; o < 32; o <<= 1) {
        int t = __shfl_up_sync(0xffffffffu, p, o);
        if (lane >= o) p += t;
    }
    int tot = __shfl_sync(0xffffffffu, p, 31);
    int base = 0;
    if (lane == 31) base = atomicAdd(&g_total, tot);
    base = __shfl_sync(0xffffffffu, base, 31);
    if (i < NN) {
        int off = base + p - d;
        g_off[i] = off;
        g_cur[i] = off;
        g_dinv[i] = rsqrtf((float)(d + 1));
    }
}

__global__ void scatter_kernel(const void* __restrict__ ei) {
    int is64 = g_is64;
    int e = blockIdx.x * blockDim.x + threadIdx.x;
    if (e < EE) {
        int s, d;
        if (is64) {
            s = (int)((const long long*)ei)[e];
            d = (int)((const long long*)ei)[EE + e];
        } else {
            s = ((const int*)ei)[e];
            d = ((const int*)ei)[EE + e];
        }
        int pos = atomicAdd(&g_cur[d], 1);
        g_csr[pos] = s;
    }
}

// -------- GEMM1 (fp16 tensor core): t1h[N,64] = dinv .* (x[N,1024] @ Wg1) --------
__global__ __launch_bounds__(256, 3) void gemm1_mma_kernel(const float* __restrict__ x) {
    __shared__ __align__(16) unsigned Bs[3 * 512];
    int tid = threadIdx.x;
    int wid = tid >> 5, lane = tid & 31;
    int gid = lane >> 2, tid4 = lane & 3;
    long long rowBase = (long long)blockIdx.x * 128 + wid * 16;

    long long r0 = rowBase + gid;
    long long r1 = r0 + 8;
    long long c0 = (r0 < NN) ? r0 : NN - 1;
    long long c1 = (r1 < NN) ? r1 : NN - 1;
    const float* p0 = x + c0 * CIN;
    const float* p1 = x + c1 * CIN;

    unsigned sbase = (unsigned)__cvta_generic_to_shared(Bs);
    int doCp = (tid < 128);

    if (doCp) cp16(sbase + tid * 16, g_Wg1p + tid * 4);
    cp_commit();
    if (doCp) cp16(sbase + 512 * 4 + tid * 16, g_Wg1p + 512 + tid * 4);
    cp_commit();

    float acc[8][4];
#pragma unroll
    for (int nb = 0; nb < 8; nb++)
#pragma unroll
        for (int q = 0; q < 4; q++) acc[nb][q] = 0.f;

    float2 a0, a1, a2, a3;
    {
        int col = tid4 * 2;
        a0 = *(const float2*)(p0 + col);
        a1 = *(const float2*)(p1 + col);
        a2 = *(const float2*)(p0 + col + 8);
        a3 = *(const float2*)(p1 + col + 8);
    }

    for (int kc = 0; kc < 64; kc++) {
        float2 n0, n1, n2, n3;
        if (kc < 63) {
            int col = (kc + 1) * 16 + tid4 * 2;
            n0 = *(const float2*)(p0 + col);
            n1 = *(const float2*)(p1 + col);
            n2 = *(const float2*)(p0 + col + 8);
            n3 = *(const float2*)(p1 + col + 8);
        }

        cp_wait1();
        __syncthreads();
        if (kc + 2 < 64 && doCp)
            cp16(sbase + ((kc + 2) % 3) * 512 * 4 + tid * 16, g_Wg1p + (kc + 2) * 512 + tid * 4);
        cp_commit();

        unsigned at[4];
        at[0] = h2pack(a0.x, a0.y);
        at[1] = h2pack(a1.x, a1.y);
        at[2] = h2pack(a2.x, a2.y);
        at[3] = h2pack(a3.x, a3.y);

        const unsigned* BsS = Bs + (kc % 3) * 512;
#pragma unroll
        for (int nb = 0; nb < 8; nb++) {
            uint2 b = *(const uint2*)(BsS + nb * 64 + lane * 2);
            mma16816h(acc[nb], at, b.x, b.y);
        }
        a0 = n0; a1 = n1; a2 = n2; a3 = n3;
    }

    float di0 = (r0 < NN) ? g_dinv[r0] : 0.f;
    float di1 = (r1 < NN) ? g_dinv[r1] : 0.f;
#pragma unroll
    for (int nb = 0; nb < 8; nb++) {
        int w = nb * 4 + tid4;
        if (r0 < NN) g_t1h[r0 * 32 + w] = h2pack(acc[nb][0] * di0, acc[nb][1] * di0);
        if (r1 < NN) g_t1h[r1 * 32 + w] = h2pack(acc[nb][2] * di1, acc[nb][3] * di1);
    }
}

// ------- gather1: 2 nodes per warp; plain-sum aggregate; t2h = dinv.*(relu@Wg2) -------
__global__ __launch_bounds__(256) void gather1_kernel(const float* __restrict__ bg1,
                                                      const float* __restrict__ Wg2) {
    __shared__ float Wg2s[HD * ZDIM];
    __shared__ float bg1s[HD];
    int tid = threadIdx.x;
    for (int i = tid; i < HD * ZDIM; i += 256) Wg2s[i] = Wg2[i];
    if (tid < HD) bg1s[tid] = bg1[tid];
    __syncthreads();

    int w = tid >> 5, lane = tid & 31;
    int vA = blockIdx.x * 16 + w * 2;
    if (vA >= NN) return;
    int vB = vA + 1;
    int hasB = (vB < NN);
    int lp = lane & 15, half = lane >> 4;

    int begA = g_off[vA], cntA = g_deg[vA];
    int begB = hasB ? g_off[vB] : 0;
    int cntB = hasB ? g_deg[vB] : 0;
    int beg = half ? begB : begA;
    int cnt = half ? cntB : cntA;
    int maxCnt = (cntA > cntB) ? cntA : cntB;

    float aA0e = 0.f, aA0o = 0.f, aA1e = 0.f, aA1o = 0.f;
    float aB0e = 0.f, aB0o = 0.f, aB1e = 0.f, aB1o = 0.f;

    for (int base = 0; base < maxCnt; base += 16) {
        int j = base + lp;
        int soff = (j < cnt) ? g_csr[beg + j] * 32 : NN * 32;
        int rem = maxCnt - base;
        if (rem > 16) rem = 16;
#pragma unroll
        for (int qq = 0; qq < 2; qq++) {
            if (qq * 8 >= rem) break;
#pragma unroll
            for (int qi = 0; qi < 8; qi++) {
                int q = qq * 8 + qi;
                int ovA = __shfl_sync(0xffffffffu, soff, q);
                int ovB = __shfl_sync(0xffffffffu, soff, 16 + q);
                float2 fA = h2unpack(g_t1h[ovA + lane]);
                float2 fB = h2unpack(g_t1h[ovB + lane]);
                if (qi & 1) { aA0o += fA.x; aA1o += fA.y; aB0o += fB.x; aB1o += fB.y; }
                else        { aA0e += fA.x; aA1e += fA.y; aB0e += fB.x; aB1e += fB.y; }
            }
        }
    }

    // epilogue node A
    {
        float di = g_dinv[vA];
        float2 pv = h2unpack(g_t1h[(long long)vA * 32 + lane]);
        float h0 = fmaxf(di * (aA0e + aA0o + pv.x) + bg1s[2 * lane],     0.f);
        float h1 = fmaxf(di * (aA1e + aA1o + pv.y) + bg1s[2 * lane + 1], 0.f);
        float z = 0.f;
#pragma unroll
        for (int k = 0; k < 32; k++) {
            float h0v = __shfl_sync(0xffffffffu, h0, k);
            float h1v = __shfl_sync(0xffffffffu, h1, k);
            z += h0v * Wg2s[(2 * k) * ZDIM + lane] + h1v * Wg2s[(2 * k + 1) * ZDIM + lane];
        }
        ((__half*)g_t2h)[(long long)vA * 32 + lane] = __float2half_rn(di * z);
    }
    // epilogue node B
    if (hasB) {
        float di = g_dinv[vB];
        float2 pv = h2unpack(g_t1h[(long long)vB * 32 + lane]);
        float h0 = fmaxf(di * (aB0e + aB0o + pv.x) + bg1s[2 * lane],     0.f);
        float h1 = fmaxf(di * (aB1e + aB1o + pv.y) + bg1s[2 * lane + 1], 0.f);
        float z = 0.f;
#pragma unroll
        for (int k = 0; k < 32; k++) {
            float h0v = __shfl_sync(0xffffffffu, h0, k);
            float h1v = __shfl_sync(0xffffffffu, h1, k);
            z += h0v * Wg2s[(2 * k) * ZDIM + lane] + h1v * Wg2s[(2 * k + 1) * ZDIM + lane];
        }
        ((__half*)g_t2h)[(long long)vB * 32 + lane] = __float2half_rn(di * z);
    }
}

// -- gather2: half-warp per node (width-16 shuffles); d = relu(z@Wf1+bf1) fp16 --
__global__ __launch_bounds__(256) void gather2_kernel(const float* __restrict__ bg2,
                                                      const float* __restrict__ Wf1,
                                                      const float* __restrict__ bf1) {
    __shared__ float Wf1s[ZDIM * HD];
    __shared__ float bg2s[ZDIM];
    __shared__ float bf1s[HD];
    int tid = threadIdx.x;
    for (int i = tid; i < ZDIM * HD; i += 256) Wf1s[i] = Wf1[i];
    if (tid < ZDIM) bg2s[tid] = bg2[tid];
    if (tid < HD)   bf1s[tid] = bf1[tid];
    __syncthreads();

    int w = tid >> 5, lane = tid & 31;
    int lp = lane & 15, half = lane >> 4;
    int v = blockIdx.x * 16 + w * 2 + half;
    int valid = (v < NN);
    int cv = valid ? v : NN - 1;

    int beg = g_off[cv];
    int cnt = valid ? g_deg[cv] : 0;

    float a0e = 0.f, a0o = 0.f, a1e = 0.f, a1o = 0.f;
    for (int base = 0; base < cnt; base += 16) {
        int j = base + lp;
        int soff = (j < cnt) ? g_csr[beg + j] * 16 : NN * 16;
        int rem = cnt - base;
        if (rem > 16) rem = 16;
#pragma unroll
        for (int qq = 0; qq < 2; qq++) {
            if (qq * 8 >= rem) break;
#pragma unroll
            for (int qi = 0; qi < 8; qi++) {
                int ov = __shfl_sync(0xffffffffu, soff, qq * 8 + qi, 16);
                float2 f = h2unpack(g_t2h[ov + lp]);
                if (qi & 1) { a0o += f.x; a1o += f.y; }
                else        { a0e += f.x; a1e += f.y; }
            }
        }
    }

    float di = g_dinv[cv];
    float2 pv = h2unpack(g_t2h[(long long)cv * 16 + lp]);
    float z0 = di * (a0e + a0o + pv.x) + bg2s[2 * lp];
    float z1 = di * (a1e + a1o + pv.y) + bg2s[2 * lp + 1];

    float e0 = 0.f, e1 = 0.f, e2 = 0.f, e3 = 0.f;
#pragma unroll
    for (int k = 0; k < 16; k++) {
        float z0v = __shfl_sync(0xffffffffu, z0, k, 16);
        float z1v = __shfl_sync(0xffffffffu, z1, k, 16);
        const float* w0 = Wf1s + (2 * k) * HD;
        const float* w1 = Wf1s + (2 * k + 1) * HD;
        e0 += z0v * w0[lp]      + z1v * w1[lp];
        e1 += z0v * w0[lp + 16] + z1v * w1[lp + 16];
        e2 += z0v * w0[lp + 32] + z1v * w1[lp + 32];
        e3 += z0v * w0[lp + 48] + z1v * w1[lp + 48];
    }
    if (valid) {
        __half* dz = (__half*)g_dzp;
        long long b = (long long)v * HD;
        dz[b + lp]      = __float2half_rn(fmaxf(e0 + bf1s[lp],      0.f));
        dz[b + lp + 16] = __float2half_rn(fmaxf(e1 + bf1s[lp + 16], 0.f));
        dz[b + lp + 32] = __float2half_rn(fmaxf(e2 + bf1s[lp + 32], 0.f));
        dz[b + lp + 48] = __float2half_rn(fmaxf(e3 + bf1s[lp + 48], 0.f));
    }
}

// ---- decode2 (fp16 tensor core): out = relu(d[N,64] @ Wf2[64,1024] + bf2) ----
__global__ __launch_bounds__(256, 3) void decode2_mma_kernel(const float* __restrict__ bf2,
                                                             float* __restrict__ out) {
    int tid = threadIdx.x;
    int wid = tid >> 5, lane = tid & 31;
    int gid = lane >> 2, tid4 = lane & 3;
    int warpM = wid & 3, warpN = wid >> 2;
    long long rowBase = (long long)blockIdx.x * 64 + warpM * 16;
    int colBase = blockIdx.y * 128 + warpN * 64;

    long long r0 = rowBase + gid;
    long long r1 = r0 + 8;
    long long c0 = (r0 < NN) ? r0 : NN - 1;
    long long c1 = (r1 < NN) ? r1 : NN - 1;
    long long rp0 = c0 * 32, rp1 = c1 * 32;

    float acc[8][4];
#pragma unroll
    for (int nb = 0; nb < 8; nb++)
#pragma unroll
        for (int q = 0; q < 4; q++) acc[nb][q] = 0.f;

#pragma unroll
    for (int kc = 0; kc < 4; kc++) {
        unsigned a[4];
        a[0] = g_dzp[rp0 + kc * 8 + tid4];
        a[1] = g_dzp[rp1 + kc * 8 + tid4];
        a[2] = g_dzp[rp0 + kc * 8 + tid4 + 4];
        a[3] = g_dzp[rp1 + kc * 8 + tid4 + 4];
#pragma unroll
        for (int nb = 0; nb < 8; nb++) {
            int nbg = colBase / 8 + nb;
            uint2 b = *(const uint2*)(g_Wf2p + (kc * 128 + nbg) * 64 + lane * 2);
            mma16816h(acc[nb], a, b.x, b.y);
        }
    }

#pragma unroll
    for (int nb = 0; nb < 8; nb++) {
        int c = colBase + nb * 8 + tid4 * 2;
        float2 bv = *(const float2*)(bf2 + c);
        if (r0 < NN) {
            float2 o = make_float2(fmaxf(acc[nb][0] + bv.x, 0.f),
                                   fmaxf(acc[nb][1] + bv.y, 0.f));
            *(float2*)(out + r0 * CIN + c) = o;
        }
        if (r1 < NN) {
            float2 o = make_float2(fmaxf(acc[nb][2] + bv.x, 0.f),
                                   fmaxf(acc[nb][3] + bv.y, 0.f));
            *(float2*)(out + r1 * CIN + c) = o;
        }
    }
}

// ---------------------------------------------------------------------------
extern "C" void kernel_launch(void* const* d_in, const int* in_sizes, int n_in,
                              void* d_out, int out_size) {
    const float* x    = (const float*)d_in[0];
    const void*  ei   = d_in[1];
    const float* Wg1  = (const float*)d_in[2];
    const float* bg1  = (const float*)d_in[3];
    const float* Wg2  = (const float*)d_in[4];
    const float* bg2  = (const float*)d_in[5];
    const float* Wf1  = (const float*)d_in[6];
    const float* bf1  = (const float*)d_in[7];
    const float* Wf2  = (const float*)d_in[8];
    const float* bf2  = (const float*)d_in[9];
    float* out = (float*)d_out;

    prep_kernel<<<NBLK, 256>>>((const int*)ei, Wg1, Wf2);           // 1
    hist_kernel<<<EE / 256, 256>>>(ei);                             // 2
    alloc_kernel<<<NBLK, 256>>>();                                  // 3
    gemm1_mma_kernel<<<(NN + 127) / 128, 256>>>(x);                 // 4 <- profiled

    scatter_kernel<<<EE / 256, 256>>>(ei);                          // 5
    gather1_kernel<<<(NN + 15) / 16, 256>>>(bg1, Wg2);              // 6
    gather2_kernel<<<(NN + 15) / 16, 256>>>(bg2, Wf1, bf1);         // 7

    dim3 g2((NN + 63) / 64, CIN / 128);
    decode2_mma_kernel<<<g2, 256>>>(bf2, out);                      // 8
}

// round 13
// speedup vs baseline: 1.1005x; 1.1005x over previous
#include <cuda_runtime.h>
#include <cuda_fp16.h>

#define NN   100000
#define EE   1600000
#define CIN  1024
#define HD   64
#define ZDIM 32

#define NBLK ((NN + 255) / 256)    // 391
#define HISTB (EE / 256)           // 6250
#define PACKB 128                  // 32768 / 256
#define GEMMB ((NN + 127) / 128)   // 782

// ---------------- scratch (static __device__ — zero-initialized) ----------------
__device__ int   g_total;                 // reset by decode2 tail each run
__device__ int   g_deg[NN];               // re-zeroed by decode2 tail each run
__device__ int   g_off[NN];
__device__ int   g_cur[NN];
__device__ int   g_csr[EE];
__device__ float g_dinv[NN];
__device__ unsigned g_t1h[NN * 32 + 32];  // dinv-scaled x@Wg1, fp16 half2 (+zero pad row, never written)
__device__ unsigned g_t2h[NN * 16 + 16];  // dinv-scaled encoder z, fp16 half2 (+zero pad row)
__device__ unsigned g_dzp[NN * 32];       // decoder hidden, fp16 half2 words

__device__ __align__(16) unsigned g_Wg1p[64 * 8 * 64];     // 128 KB
__device__ __align__(16) unsigned g_Wf2p[4 * 128 * 64];    // 128 KB

// ---------------- helpers ----------------
__device__ __forceinline__ unsigned h2pack(float x0, float x1) {
    __half2 h = __float22half2_rn(make_float2(x0, x1));
    return *reinterpret_cast<unsigned*>(&h);
}
__device__ __forceinline__ float2 h2unpack(unsigned w) {
    return __half22float2(*reinterpret_cast<__half2*>(&w));
}

__device__ __forceinline__ void mma16816h(float* c, const unsigned* a, unsigned b0, unsigned b1) {
    asm volatile(
        "mma.sync.aligned.m16n8k16.row.col.f32.f16.f16.f32 "
        "{%0,%1,%2,%3}, {%4,%5,%6,%7}, {%8,%9}, {%0,%1,%2,%3};\n"
        : "+f"(c[0]), "+f"(c[1]), "+f"(c[2]), "+f"(c[3])
        : "r"(a[0]), "r"(a[1]), "r"(a[2]), "r"(a[3]), "r"(b0), "r"(b1));
}

__device__ __forceinline__ void cp16(unsigned smem_addr, const void* gptr) {
    asm volatile("cp.async.ca.shared.global [%0], [%1], 16;\n"
                 :: "r"(smem_addr), "l"(gptr));
}
__device__ __forceinline__ void cp_commit() { asm volatile("cp.async.commit_group;\n"); }
__device__ __forceinline__ void cp_wait1()  { asm volatile("cp.async.wait_group 1;\n" ::: "memory"); }

// per-block edge-dtype detection (int64 little-endian => odd 32-bit words all zero)
__device__ __forceinline__ int detect_is64_block(const int* ei32, int* s_flag) {
    if (threadIdx.x == 0) {
        int nz = 0;
#pragma unroll
        for (int k = 0; k < 16; k++) nz |= (ei32[2 * k + 1] != 0);
        *s_flag = nz ? 0 : 1;
    }
    __syncthreads();
    return *s_flag;
}

__device__ __forceinline__ void pack_one(const float* __restrict__ W, int K, int N,
                                         unsigned* __restrict__ pw, int idx) {
    int lane2 = idx & 63;
    int j = lane2 & 1;
    int lane = lane2 >> 1;
    int nb = (idx >> 6) % (N / 8);
    int kc = idx / (64 * (N / 8));
    int k0 = kc * 16 + (lane & 3) * 2 + j * 8;
    int n = nb * 8 + (lane >> 2);
    pw[idx] = h2pack(W[(long long)k0 * N + n], W[(long long)(k0 + 1) * N + n]);
}

// ---------------- launch 1: hist (edge histogram) + weight packing ----------------
__global__ void histprep_kernel(const void* __restrict__ ei,
                                const float* __restrict__ Wg1,
                                const float* __restrict__ Wf2) {
    __shared__ int s_is64;
    int b = blockIdx.x;
    if (b < HISTB) {
        int is64 = detect_is64_block((const int*)ei, &s_is64);
        int e = b * 256 + threadIdx.x;
        int d = is64 ? (int)((const long long*)ei)[EE + e]
                     : ((const int*)ei)[EE + e];
        atomicAdd(&g_deg[d], 1);
    } else {
        int idx = (b - HISTB) * 256 + threadIdx.x;   // 0..32767
        pack_one(Wg1, CIN, HD, g_Wg1p, idx);
        pack_one(Wf2, HD, CIN, g_Wf2p, idx);
    }
}

// ---------------- launch 2: alloc (warp-aggregated offsets + dinv) ----------------
__global__ void alloc_kernel() {
    int i = blockIdx.x * blockDim.x + threadIdx.x;
    int lane = threadIdx.x & 31;
    int d = (i < NN) ? g_deg[i] : 0;
    int p = d;
#pragma unroll
    for (int o = 1; o < 32; o <<= 1) {
        int t = __shfl_up_sync(0xffffffffu, p, o);
        if (lane >= o) p += t;
    }
    int tot = __shfl_sync(0xffffffffu, p, 31);
    int base = 0;
    if (lane == 31) base = atomicAdd(&g_total, tot);
    base = __shfl_sync(0xffffffffu, base, 31);
    if (i < NN) {
        int off = base + p - d;
        g_off[i] = off;
        g_cur[i] = off;
        g_dinv[i] = rsqrtf((float)(d + 1));
    }
}

// ---------------- launch 3: gemm1 (blocks 0..GEMMB-1) + scatter (rest) ----------------
__global__ __launch_bounds__(256, 3) void gemmscat_kernel(const float* __restrict__ x,
                                                          const void* __restrict__ ei) {
    __shared__ __align__(16) unsigned Bs[3 * 512];
    __shared__ int s_is64;
    int tid = threadIdx.x;

    if (blockIdx.x >= GEMMB) {
        // ---- scatter path ----
        int is64 = detect_is64_block((const int*)ei, &s_is64);
        int e = (blockIdx.x - GEMMB) * 256 + tid;
        int s, d;
        if (is64) {
            s = (int)((const long long*)ei)[e];
            d = (int)((const long long*)ei)[EE + e];
        } else {
            s = ((const int*)ei)[e];
            d = ((const int*)ei)[EE + e];
        }
        int pos = atomicAdd(&g_cur[d], 1);
        g_csr[pos] = s;
        return;
    }

    // ---- gemm1 path: t1h[N,64] = dinv .* (x[N,1024] @ Wg1) ----
    int wid = tid >> 5, lane = tid & 31;
    int gid = lane >> 2, tid4 = lane & 3;
    long long rowBase = (long long)blockIdx.x * 128 + wid * 16;

    long long r0 = rowBase + gid;
    long long r1 = r0 + 8;
    long long c0 = (r0 < NN) ? r0 : NN - 1;
    long long c1 = (r1 < NN) ? r1 : NN - 1;
    const float* p0 = x + c0 * CIN;
    const float* p1 = x + c1 * CIN;

    unsigned sbase = (unsigned)__cvta_generic_to_shared(Bs);
    int doCp = (tid < 128);

    if (doCp) cp16(sbase + tid * 16, g_Wg1p + tid * 4);
    cp_commit();
    if (doCp) cp16(sbase + 512 * 4 + tid * 16, g_Wg1p + 512 + tid * 4);
    cp_commit();

    float acc[8][4];
#pragma unroll
    for (int nb = 0; nb < 8; nb++)
#pragma unroll
        for (int q = 0; q < 4; q++) acc[nb][q] = 0.f;

    float2 a0, a1, a2, a3;
    {
        int col = tid4 * 2;
        a0 = *(const float2*)(p0 + col);
        a1 = *(const float2*)(p1 + col);
        a2 = *(const float2*)(p0 + col + 8);
        a3 = *(const float2*)(p1 + col + 8);
    }

    for (int kc = 0; kc < 64; kc++) {
        float2 n0, n1, n2, n3;
        if (kc < 63) {
            int col = (kc + 1) * 16 + tid4 * 2;
            n0 = *(const float2*)(p0 + col);
            n1 = *(const float2*)(p1 + col);
            n2 = *(const float2*)(p0 + col + 8);
            n3 = *(const float2*)(p1 + col + 8);
        }

        cp_wait1();
        __syncthreads();
        if (kc + 2 < 64 && doCp)
            cp16(sbase + ((kc + 2) % 3) * 512 * 4 + tid * 16, g_Wg1p + (kc + 2) * 512 + tid * 4);
        cp_commit();

        unsigned at[4];
        at[0] = h2pack(a0.x, a0.y);
        at[1] = h2pack(a1.x, a1.y);
        at[2] = h2pack(a2.x, a2.y);
        at[3] = h2pack(a3.x, a3.y);

        const unsigned* BsS = Bs + (kc % 3) * 512;
#pragma unroll
        for (int nb = 0; nb < 8; nb++) {
            uint2 b = *(const uint2*)(BsS + nb * 64 + lane * 2);
            mma16816h(acc[nb], at, b.x, b.y);
        }
        a0 = n0; a1 = n1; a2 = n2; a3 = n3;
    }

    float di0 = (r0 < NN) ? g_dinv[r0] : 0.f;
    float di1 = (r1 < NN) ? g_dinv[r1] : 0.f;
#pragma unroll
    for (int nb = 0; nb < 8; nb++) {
        int w = nb * 4 + tid4;
        if (r0 < NN) g_t1h[r0 * 32 + w] = h2pack(acc[nb][0] * di0, acc[nb][1] * di0);
        if (r1 < NN) g_t1h[r1 * 32 + w] = h2pack(acc[nb][2] * di1, acc[nb][3] * di1);
    }
}

// ------- launch 4 (profiled): gather1 — R11 shape, 1 warp/node -------
__global__ __launch_bounds__(256) void gather1_kernel(const float* __restrict__ bg1,
                                                      const float* __restrict__ Wg2) {
    __shared__ float Wg2s[HD * ZDIM];
    __shared__ float bg1s[HD];
    int tid = threadIdx.x;
    for (int i = tid; i < HD * ZDIM; i += 256) Wg2s[i] = Wg2[i];
    if (tid < HD) bg1s[tid] = bg1[tid];
    __syncthreads();

    int v = blockIdx.x * 8 + (tid >> 5);
    if (v >= NN) return;
    int lane = tid & 31;

    float a0a = 0.f, a0b = 0.f, a1a = 0.f, a1b = 0.f;
    int beg = g_off[v];
    int cnt = g_deg[v];
    for (int base = 0; base < cnt; base += 32) {
        int j = base + lane;
        int soff = (j < cnt) ? g_csr[beg + j] * 32 : NN * 32;
        int rem = cnt - base;
        if (rem > 32) rem = 32;
#pragma unroll
        for (int qq = 0; qq < 4; qq++) {
            if (qq * 8 >= rem) break;
#pragma unroll
            for (int qi = 0; qi < 8; qi++) {
                int ov = __shfl_sync(0xffffffffu, soff, qq * 8 + qi);
                float2 f = h2unpack(g_t1h[ov + lane]);
                if (qi & 1) { a0b += f.x; a1b += f.y; }
                else        { a0a += f.x; a1a += f.y; }
            }
        }
    }
    float di = g_dinv[v];
    float2 pv = h2unpack(g_t1h[(long long)v * 32 + lane]);
    float h0 = fmaxf(di * (a0a + a0b + pv.x) + bg1s[2 * lane],     0.f);
    float h1 = fmaxf(di * (a1a + a1b + pv.y) + bg1s[2 * lane + 1], 0.f);

    float z = 0.f;
#pragma unroll
    for (int k = 0; k < 32; k++) {
        float h0v = __shfl_sync(0xffffffffu, h0, k);
        float h1v = __shfl_sync(0xffffffffu, h1, k);
        z += h0v * Wg2s[(2 * k) * ZDIM + lane] + h1v * Wg2s[(2 * k + 1) * ZDIM + lane];
    }
    ((__half*)g_t2h)[(long long)v * 32 + lane] = __float2half_rn(di * z);
}

// -- launch 5: gather2 — R11 shape --
__global__ __launch_bounds__(256) void gather2_kernel(const float* __restrict__ bg2,
                                                      const float* __restrict__ Wf1,
                                                      const float* __restrict__ bf1) {
    __shared__ float Wf1s[ZDIM * HD];
    __shared__ float bg2s[ZDIM];
    __shared__ float bf1s[HD];
    int tid = threadIdx.x;
    for (int i = tid; i < ZDIM * HD; i += 256) Wf1s[i] = Wf1[i];
    if (tid < ZDIM) bg2s[tid] = bg2[tid];
    if (tid < HD)   bf1s[tid] = bf1[tid];
    __syncthreads();

    int v = blockIdx.x * 8 + (tid >> 5);
    if (v >= NN) return;
    int lane = tid & 31;
    int lp = lane & 15;

    float a0e = 0.f, a0o = 0.f, a1e = 0.f, a1o = 0.f;
    int beg = g_off[v];
    int cnt = g_deg[v];
    for (int base = 0; base < cnt; base += 32) {
        int j = base + lane;
        int soff = (j < cnt) ? g_csr[beg + j] * 16 : NN * 16;
        int rem = cnt - base;
        if (rem > 32) rem = 32;
#pragma unroll
        for (int qq = 0; qq < 4; qq++) {
            if (qq * 8 >= rem) break;
#pragma unroll
            for (int qi = 0; qi < 8; qi++) {
                int ov = __shfl_sync(0xffffffffu, soff, qq * 8 + qi);
                float2 f = h2unpack(g_t2h[ov + lp]);
                if (qi & 1) { a0o += f.x; a1o += f.y; }
                else        { a0e += f.x; a1e += f.y; }
            }
        }
    }
    float di = g_dinv[v];
    float2 pv = h2unpack(g_t2h[(long long)v * 16 + lp]);
    float z0 = di * (a0e + a0o + pv.x) + bg2s[2 * lp];
    float z1 = di * (a1e + a1o + pv.y) + bg2s[2 * lp + 1];

    float e0 = 0.f, e1 = 0.f;
#pragma unroll
    for (int k = 0; k < 16; k++) {
        float z0v = __shfl_sync(0xffffffffu, z0, k);
        float z1v = __shfl_sync(0xffffffffu, z1, k);
        e0 += z0v * Wf1s[(2 * k) * HD + lane]      + z1v * Wf1s[(2 * k + 1) * HD + lane];
        e1 += z0v * Wf1s[(2 * k) * HD + lane + 32] + z1v * Wf1s[(2 * k + 1) * HD + lane + 32];
    }
    float d0 = fmaxf(e0 + bf1s[lane],      0.f);
    float d1 = fmaxf(e1 + bf1s[lane + 32], 0.f);

    __half* dz = (__half*)g_dzp;
    long long b = (long long)v * HD;
    dz[b + lane]      = __float2half_rn(d0);
    dz[b + lane + 32] = __float2half_rn(d1);
}

// ---- launch 6: decode2 + tail cleanup (re-zero g_deg, reset g_total) ----
__global__ __launch_bounds__(256, 3) void decode2_mma_kernel(const float* __restrict__ bf2,
                                                             float* __restrict__ out) {
    int tid = threadIdx.x;

    // tail cleanup for next replay (runs after all g_deg consumers)
    if (blockIdx.y == 0) {
        int i = blockIdx.x * 256 + tid;
        if (i < NN) g_deg[i] = 0;
        if (i == 0) g_total = 0;
    }

    int wid = tid >> 5, lane = tid & 31;
    int gid = lane >> 2, tid4 = lane & 3;
    int warpM = wid & 3, warpN = wid >> 2;
    long long rowBase = (long long)blockIdx.x * 64 + warpM * 16;
    int colBase = blockIdx.y * 128 + warpN * 64;

    long long r0 = rowBase + gid;
    long long r1 = r0 + 8;
    long long c0 = (r0 < NN) ? r0 : NN - 1;
    long long c1 = (r1 < NN) ? r1 : NN - 1;
    long long rp0 = c0 * 32, rp1 = c1 * 32;

    float acc[8][4];
#pragma unroll
    for (int nb = 0; nb < 8; nb++)
#pragma unroll
        for (int q = 0; q < 4; q++) acc[nb][q] = 0.f;

#pragma unroll
    for (int kc = 0; kc < 4; kc++) {
        unsigned a[4];
        a[0] = g_dzp[rp0 + kc * 8 + tid4];
        a[1] = g_dzp[rp1 + kc * 8 + tid4];
        a[2] = g_dzp[rp0 + kc * 8 + tid4 + 4];
        a[3] = g_dzp[rp1 + kc * 8 + tid4 + 4];
#pragma unroll
        for (int nb = 0; nb < 8; nb++) {
            int nbg = colBase / 8 + nb;
            uint2 b = *(const uint2*)(g_Wf2p + (kc * 128 + nbg) * 64 + lane * 2);
            mma16816h(acc[nb], a, b.x, b.y);
        }
    }

#pragma unroll
    for (int nb = 0; nb < 8; nb++) {
        int c = colBase + nb * 8 + tid4 * 2;
        float2 bv = *(const float2*)(bf2 + c);
        if (r0 < NN) {
            float2 o = make_float2(fmaxf(acc[nb][0] + bv.x, 0.f),
                                   fmaxf(acc[nb][1] + bv.y, 0.f));
            *(float2*)(out + r0 * CIN + c) = o;
        }
        if (r1 < NN) {
            float2 o = make_float2(fmaxf(acc[nb][2] + bv.x, 0.f),
                                   fmaxf(acc[nb][3] + bv.y, 0.f));
            *(float2*)(out + r1 * CIN + c) = o;
        }
    }
}

// ---------------------------------------------------------------------------
extern "C" void kernel_launch(void* const* d_in, const int* in_sizes, int n_in,
                              void* d_out, int out_size) {
    const float* x    = (const float*)d_in[0];
    const void*  ei   = d_in[1];
    const float* Wg1  = (const float*)d_in[2];
    const float* bg1  = (const float*)d_in[3];
    const float* Wg2  = (const float*)d_in[4];
    const float* bg2  = (const float*)d_in[5];
    const float* Wf1  = (const float*)d_in[6];
    const float* bf1  = (const float*)d_in[7];
    const float* Wf2  = (const float*)d_in[8];
    const float* bf2  = (const float*)d_in[9];
    float* out = (float*)d_out;

    histprep_kernel<<<HISTB + PACKB, 256>>>(ei, Wg1, Wf2);          // 1
    alloc_kernel<<<NBLK, 256>>>();                                  // 2
    gemmscat_kernel<<<GEMMB + HISTB, 256>>>(x, ei);                 // 3
    gather1_kernel<<<(NN + 7) / 8, 256>>>(bg1, Wg2);                // 4 <- profiled

    gather2_kernel<<<(NN + 7) / 8, 256>>>(bg2, Wf1, bf1);           // 5

    dim3 g2((NN + 63) / 64, CIN / 128);
    decode2_mma_kernel<<<g2, 256>>>(bf2, out);                      // 6
}

// round 14
// speedup vs baseline: 1.2861x; 1.1686x over previous
#include <cuda_runtime.h>
#include <cuda_fp16.h>

#define NN   100000
#define EE   1600000
#define CIN  1024
#define HD   64
#define ZDIM 32

#define NBLK ((NN + 255) / 256)    // 391
#define HISTB (EE / 256)           // 6250
#define PACKB 128                  // 32768 / 256
#define GEMMB ((NN + 127) / 128)   // 782

// ---------------- scratch (static __device__ — zero-initialized) ----------------
__device__ int   g_total;                 // reset by decode2 tail each run
__device__ int   g_deg[NN];               // re-zeroed by decode2 tail each run
__device__ int   g_off[NN];
__device__ int   g_cur[NN];
__device__ int   g_csr[EE];
__device__ float g_dinv[NN];
__device__ unsigned g_t1h[NN * 32 + 32];  // dinv-scaled x@Wg1, fp16 half2 (+zero pad row)
__device__ unsigned g_hh[NN * 32];        // encoder hidden h (post-relu), fp16 half2
__device__ unsigned g_t2h[NN * 16 + 16];  // dinv-scaled t2 = h@Wg2, fp16 half2 (+zero pad row)
__device__ unsigned g_zh[NN * 16];        // encoder output z, fp16 half2
__device__ unsigned g_dzp[NN * 32];       // decoder hidden, fp16 half2 words

__device__ __align__(16) unsigned g_Wg1p[64 * 8 * 64];     // 128 KB
__device__ __align__(16) unsigned g_Wf2p[4 * 128 * 64];    // 128 KB
__device__ __align__(16) unsigned g_Wg2p[4 * 4 * 64];      // 4 KB  (K=64, N=32)
__device__ __align__(16) unsigned g_Wf1p[2 * 8 * 64];      // 4 KB  (K=32, N=64)

// ---------------- helpers ----------------
__device__ __forceinline__ unsigned h2pack(float x0, float x1) {
    __half2 h = __float22half2_rn(make_float2(x0, x1));
    return *reinterpret_cast<unsigned*>(&h);
}
__device__ __forceinline__ float2 h2unpack(unsigned w) {
    return __half22float2(*reinterpret_cast<__half2*>(&w));
}

__device__ __forceinline__ void mma16816h(float* c, const unsigned* a, unsigned b0, unsigned b1) {
    asm volatile(
        "mma.sync.aligned.m16n8k16.row.col.f32.f16.f16.f32 "
        "{%0,%1,%2,%3}, {%4,%5,%6,%7}, {%8,%9}, {%0,%1,%2,%3};\n"
        : "+f"(c[0]), "+f"(c[1]), "+f"(c[2]), "+f"(c[3])
        : "r"(a[0]), "r"(a[1]), "r"(a[2]), "r"(a[3]), "r"(b0), "r"(b1));
}

__device__ __forceinline__ void cp16(unsigned smem_addr, const void* gptr) {
    asm volatile("cp.async.ca.shared.global [%0], [%1], 16;\n"
                 :: "r"(smem_addr), "l"(gptr));
}
__device__ __forceinline__ void cp_commit() { asm volatile("cp.async.commit_group;\n"); }
__device__ __forceinline__ void cp_wait1()  { asm volatile("cp.async.wait_group 1;\n" ::: "memory"); }

// per-block edge-dtype detection (int64 little-endian => odd 32-bit words all zero)
__device__ __forceinline__ int detect_is64_block(const int* ei32, int* s_flag) {
    if (threadIdx.x == 0) {
        int nz = 0;
#pragma unroll
        for (int k = 0; k < 16; k++) nz |= (ei32[2 * k + 1] != 0);
        *s_flag = nz ? 0 : 1;
    }
    __syncthreads();
    return *s_flag;
}

__device__ __forceinline__ void pack_one(const float* __restrict__ W, int K, int N,
                                         unsigned* __restrict__ pw, int idx) {
    int lane2 = idx & 63;
    int j = lane2 & 1;
    int lane = lane2 >> 1;
    int nb = (idx >> 6) % (N / 8);
    int kc = idx / (64 * (N / 8));
    int k0 = kc * 16 + (lane & 3) * 2 + j * 8;
    int n = nb * 8 + (lane >> 2);
    pw[idx] = h2pack(W[(long long)k0 * N + n], W[(long long)(k0 + 1) * N + n]);
}

// ---------------- launch 1: hist + weight packing (all four) ----------------
__global__ void histprep_kernel(const void* __restrict__ ei,
                                const float* __restrict__ Wg1,
                                const float* __restrict__ Wf2,
                                const float* __restrict__ Wg2,
                                const float* __restrict__ Wf1) {
    __shared__ int s_is64;
    int b = blockIdx.x;
    if (b < HISTB) {
        int is64 = detect_is64_block((const int*)ei, &s_is64);
        int e = b * 256 + threadIdx.x;
        int d = is64 ? (int)((const long long*)ei)[EE + e]
                     : ((const int*)ei)[EE + e];
        atomicAdd(&g_deg[d], 1);
    } else {
        int idx = (b - HISTB) * 256 + threadIdx.x;   // 0..32767
        pack_one(Wg1, CIN, HD, g_Wg1p, idx);
        pack_one(Wf2, HD, CIN, g_Wf2p, idx);
        if (idx < 4 * 4 * 64) pack_one(Wg2, HD, ZDIM, g_Wg2p, idx);
        if (idx < 2 * 8 * 64) pack_one(Wf1, ZDIM, HD, g_Wf1p, idx);
    }
}

// ---------------- launch 2: alloc ----------------
__global__ void alloc_kernel() {
    int i = blockIdx.x * blockDim.x + threadIdx.x;
    int lane = threadIdx.x & 31;
    int d = (i < NN) ? g_deg[i] : 0;
    int p = d;
#pragma unroll
    for (int o = 1; o < 32; o <<= 1) {
        int t = __shfl_up_sync(0xffffffffu, p, o);
        if (lane >= o) p += t;
    }
    int tot = __shfl_sync(0xffffffffu, p, 31);
    int base = 0;
    if (lane == 31) base = atomicAdd(&g_total, tot);
    base = __shfl_sync(0xffffffffu, base, 31);
    if (i < NN) {
        int off = base + p - d;
        g_off[i] = off;
        g_cur[i] = off;
        g_dinv[i] = rsqrtf((float)(d + 1));
    }
}

// ---------------- launch 3: gemm1 + scatter (fused) ----------------
__global__ __launch_bounds__(256, 3) void gemmscat_kernel(const float* __restrict__ x,
                                                          const void* __restrict__ ei) {
    __shared__ __align__(16) unsigned Bs[3 * 512];
    __shared__ int s_is64;
    int tid = threadIdx.x;

    if (blockIdx.x >= GEMMB) {
        int is64 = detect_is64_block((const int*)ei, &s_is64);
        int e = (blockIdx.x - GEMMB) * 256 + tid;
        int s, d;
        if (is64) {
            s = (int)((const long long*)ei)[e];
            d = (int)((const long long*)ei)[EE + e];
        } else {
            s = ((const int*)ei)[e];
            d = ((const int*)ei)[EE + e];
        }
        int pos = atomicAdd(&g_cur[d], 1);
        g_csr[pos] = s;
        return;
    }

    int wid = tid >> 5, lane = tid & 31;
    int gid = lane >> 2, tid4 = lane & 3;
    long long rowBase = (long long)blockIdx.x * 128 + wid * 16;

    long long r0 = rowBase + gid;
    long long r1 = r0 + 8;
    long long c0 = (r0 < NN) ? r0 : NN - 1;
    long long c1 = (r1 < NN) ? r1 : NN - 1;
    const float* p0 = x + c0 * CIN;
    const float* p1 = x + c1 * CIN;

    unsigned sbase = (unsigned)__cvta_generic_to_shared(Bs);
    int doCp = (tid < 128);

    if (doCp) cp16(sbase + tid * 16, g_Wg1p + tid * 4);
    cp_commit();
    if (doCp) cp16(sbase + 512 * 4 + tid * 16, g_Wg1p + 512 + tid * 4);
    cp_commit();

    float acc[8][4];
#pragma unroll
    for (int nb = 0; nb < 8; nb++)
#pragma unroll
        for (int q = 0; q < 4; q++) acc[nb][q] = 0.f;

    float2 a0, a1, a2, a3;
    {
        int col = tid4 * 2;
        a0 = *(const float2*)(p0 + col);
        a1 = *(const float2*)(p1 + col);
        a2 = *(const float2*)(p0 + col + 8);
        a3 = *(const float2*)(p1 + col + 8);
    }

    for (int kc = 0; kc < 64; kc++) {
        float2 n0, n1, n2, n3;
        if (kc < 63) {
            int col = (kc + 1) * 16 + tid4 * 2;
            n0 = *(const float2*)(p0 + col);
            n1 = *(const float2*)(p1 + col);
            n2 = *(const float2*)(p0 + col + 8);
            n3 = *(const float2*)(p1 + col + 8);
        }

        cp_wait1();
        __syncthreads();
        if (kc + 2 < 64 && doCp)
            cp16(sbase + ((kc + 2) % 3) * 512 * 4 + tid * 16, g_Wg1p + (kc + 2) * 512 + tid * 4);
        cp_commit();

        unsigned at[4];
        at[0] = h2pack(a0.x, a0.y);
        at[1] = h2pack(a1.x, a1.y);
        at[2] = h2pack(a2.x, a2.y);
        at[3] = h2pack(a3.x, a3.y);

        const unsigned* BsS = Bs + (kc % 3) * 512;
#pragma unroll
        for (int nb = 0; nb < 8; nb++) {
            uint2 b = *(const uint2*)(BsS + nb * 64 + lane * 2);
            mma16816h(acc[nb], at, b.x, b.y);
        }
        a0 = n0; a1 = n1; a2 = n2; a3 = n3;
    }

    float di0 = (r0 < NN) ? g_dinv[r0] : 0.f;
    float di1 = (r1 < NN) ? g_dinv[r1] : 0.f;
#pragma unroll
    for (int nb = 0; nb < 8; nb++) {
        int w = nb * 4 + tid4;
        if (r0 < NN) g_t1h[r0 * 32 + w] = h2pack(acc[nb][0] * di0, acc[nb][1] * di0);
        if (r1 < NN) g_t1h[r1 * 32 + w] = h2pack(acc[nb][2] * di1, acc[nb][3] * di1);
    }
}

// ------- launch 4 (profiled): gather1 — aggregation + relu only -------
__global__ __launch_bounds__(256) void gather1_kernel(const float* __restrict__ bg1) {
    __shared__ float bg1s[HD];
    int tid = threadIdx.x;
    if (tid < HD) bg1s[tid] = bg1[tid];
    __syncthreads();

    int v = blockIdx.x * 8 + (tid >> 5);
    if (v >= NN) return;
    int lane = tid & 31;

    float a0a = 0.f, a0b = 0.f, a1a = 0.f, a1b = 0.f;
    int beg = g_off[v];
    int cnt = g_deg[v];
    for (int base = 0; base < cnt; base += 32) {
        int j = base + lane;
        int soff = (j < cnt) ? g_csr[beg + j] * 32 : NN * 32;
        int rem = cnt - base;
        if (rem > 32) rem = 32;
#pragma unroll
        for (int qq = 0; qq < 4; qq++) {
            if (qq * 8 >= rem) break;
#pragma unroll
            for (int qi = 0; qi < 8; qi++) {
                int ov = __shfl_sync(0xffffffffu, soff, qq * 8 + qi);
                float2 f = h2unpack(g_t1h[ov + lane]);
                if (qi & 1) { a0b += f.x; a1b += f.y; }
                else        { a0a += f.x; a1a += f.y; }
            }
        }
    }
    float di = g_dinv[v];
    float2 pv = h2unpack(g_t1h[(long long)v * 32 + lane]);
    float h0 = fmaxf(di * (a0a + a0b + pv.x) + bg1s[2 * lane],     0.f);
    float h1 = fmaxf(di * (a1a + a1b + pv.y) + bg1s[2 * lane + 1], 0.f);
    g_hh[(long long)v * 32 + lane] = h2pack(h0, h1);
}

// ---- launch 5: t2 MMA — t2h = dinv .* (h[N,64] @ Wg2[64,32]) ----
__global__ __launch_bounds__(256, 3) void t2_mma_kernel() {
    int tid = threadIdx.x;
    int wid = tid >> 5, lane = tid & 31;
    int gid = lane >> 2, tid4 = lane & 3;
    long long rowBase = (long long)blockIdx.x * 128 + wid * 16;

    long long r0 = rowBase + gid;
    long long r1 = r0 + 8;
    long long c0 = (r0 < NN) ? r0 : NN - 1;
    long long c1 = (r1 < NN) ? r1 : NN - 1;
    long long rp0 = c0 * 32, rp1 = c1 * 32;

    float acc[4][4];
#pragma unroll
    for (int nb = 0; nb < 4; nb++)
#pragma unroll
        for (int q = 0; q < 4; q++) acc[nb][q] = 0.f;

#pragma unroll
    for (int kc = 0; kc < 4; kc++) {
        unsigned a[4];
        a[0] = g_hh[rp0 + kc * 8 + tid4];
        a[1] = g_hh[rp1 + kc * 8 + tid4];
        a[2] = g_hh[rp0 + kc * 8 + tid4 + 4];
        a[3] = g_hh[rp1 + kc * 8 + tid4 + 4];
#pragma unroll
        for (int nb = 0; nb < 4; nb++) {
            uint2 b = *(const uint2*)(g_Wg2p + (kc * 4 + nb) * 64 + lane * 2);
            mma16816h(acc[nb], a, b.x, b.y);
        }
    }

    float di0 = (r0 < NN) ? g_dinv[r0] : 0.f;
    float di1 = (r1 < NN) ? g_dinv[r1] : 0.f;
#pragma unroll
    for (int nb = 0; nb < 4; nb++) {
        int w = nb * 4 + tid4;
        if (r0 < NN) g_t2h[r0 * 16 + w] = h2pack(acc[nb][0] * di0, acc[nb][1] * di0);
        if (r1 < NN) g_t2h[r1 * 16 + w] = h2pack(acc[nb][2] * di1, acc[nb][3] * di1);
    }
}

// -- launch 6: gather2 — aggregation only; z stored fp16 --
__global__ __launch_bounds__(256) void gather2_kernel(const float* __restrict__ bg2) {
    __shared__ float bg2s[ZDIM];
    int tid = threadIdx.x;
    if (tid < ZDIM) bg2s[tid] = bg2[tid];
    __syncthreads();

    int v = blockIdx.x * 8 + (tid >> 5);
    if (v >= NN) return;
    int lane = tid & 31;
    int lp = lane & 15;

    float a0e = 0.f, a0o = 0.f, a1e = 0.f, a1o = 0.f;
    int beg = g_off[v];
    int cnt = g_deg[v];
    for (int base = 0; base < cnt; base += 32) {
        int j = base + lane;
        int soff = (j < cnt) ? g_csr[beg + j] * 16 : NN * 16;
        int rem = cnt - base;
        if (rem > 32) rem = 32;
#pragma unroll
        for (int qq = 0; qq < 4; qq++) {
            if (qq * 8 >= rem) break;
#pragma unroll
            for (int qi = 0; qi < 8; qi++) {
                int ov = __shfl_sync(0xffffffffu, soff, qq * 8 + qi);
                float2 f = h2unpack(g_t2h[ov + lp]);
                if (qi & 1) { a0o += f.x; a1o += f.y; }
                else        { a0e += f.x; a1e += f.y; }
            }
        }
    }
    float di = g_dinv[v];
    float2 pv = h2unpack(g_t2h[(long long)v * 16 + lp]);
    float z0 = di * (a0e + a0o + pv.x) + bg2s[2 * lp];
    float z1 = di * (a1e + a1o + pv.y) + bg2s[2 * lp + 1];
    if (lane < 16)
        g_zh[(long long)v * 16 + lp] = h2pack(z0, z1);
}

// ---- launch 7: z MMA — dzp = relu(z[N,32] @ Wf1[32,64] + bf1) ----
__global__ __launch_bounds__(256, 3) void z_mma_kernel(const float* __restrict__ bf1) {
    __shared__ float bf1s[HD];
    int tid = threadIdx.x;
    if (tid < HD) bf1s[tid] = bf1[tid];
    __syncthreads();

    int wid = tid >> 5, lane = tid & 31;
    int gid = lane >> 2, tid4 = lane & 3;
    long long rowBase = (long long)blockIdx.x * 128 + wid * 16;

    long long r0 = rowBase + gid;
    long long r1 = r0 + 8;
    long long c0 = (r0 < NN) ? r0 : NN - 1;
    long long c1 = (r1 < NN) ? r1 : NN - 1;
    long long rp0 = c0 * 16, rp1 = c1 * 16;

    float acc[8][4];
#pragma unroll
    for (int nb = 0; nb < 8; nb++)
#pragma unroll
        for (int q = 0; q < 4; q++) acc[nb][q] = 0.f;

#pragma unroll
    for (int kc = 0; kc < 2; kc++) {
        unsigned a[4];
        a[0] = g_zh[rp0 + kc * 8 + tid4];
        a[1] = g_zh[rp1 + kc * 8 + tid4];
        a[2] = g_zh[rp0 + kc * 8 + tid4 + 4];
        a[3] = g_zh[rp1 + kc * 8 + tid4 + 4];
#pragma unroll
        for (int nb = 0; nb < 8; nb++) {
            uint2 b = *(const uint2*)(g_Wf1p + (kc * 8 + nb) * 64 + lane * 2);
            mma16816h(acc[nb], a, b.x, b.y);
        }
    }

#pragma unroll
    for (int nb = 0; nb < 8; nb++) {
        int c = nb * 8 + tid4 * 2;
        float b0 = bf1s[c], b1 = bf1s[c + 1];
        int w = nb * 4 + tid4;
        if (r0 < NN)
            g_dzp[r0 * 32 + w] = h2pack(fmaxf(acc[nb][0] + b0, 0.f), fmaxf(acc[nb][1] + b1, 0.f));
        if (r1 < NN)
            g_dzp[r1 * 32 + w] = h2pack(fmaxf(acc[nb][2] + b0, 0.f), fmaxf(acc[nb][3] + b1, 0.f));
    }
}

// ---- launch 8: decode2 + tail cleanup ----
__global__ __launch_bounds__(256, 3) void decode2_mma_kernel(const float* __restrict__ bf2,
                                                             float* __restrict__ out) {
    int tid = threadIdx.x;

    if (blockIdx.y == 0) {
        int i = blockIdx.x * 256 + tid;
        if (i < NN) g_deg[i] = 0;
        if (i == 0) g_total = 0;
    }

    int wid = tid >> 5, lane = tid & 31;
    int gid = lane >> 2, tid4 = lane & 3;
    int warpM = wid & 3, warpN = wid >> 2;
    long long rowBase = (long long)blockIdx.x * 64 + warpM * 16;
    int colBase = blockIdx.y * 128 + warpN * 64;

    long long r0 = rowBase + gid;
    long long r1 = r0 + 8;
    long long c0 = (r0 < NN) ? r0 : NN - 1;
    long long c1 = (r1 < NN) ? r1 : NN - 1;
    long long rp0 = c0 * 32, rp1 = c1 * 32;

    float acc[8][4];
#pragma unroll
    for (int nb = 0; nb < 8; nb++)
#pragma unroll
        for (int q = 0; q < 4; q++) acc[nb][q] = 0.f;

#pragma unroll
    for (int kc = 0; kc < 4; kc++) {
        unsigned a[4];
        a[0] = g_dzp[rp0 + kc * 8 + tid4];
        a[1] = g_dzp[rp1 + kc * 8 + tid4];
        a[2] = g_dzp[rp0 + kc * 8 + tid4 + 4];
        a[3] = g_dzp[rp1 + kc * 8 + tid4 + 4];
#pragma unroll
        for (int nb = 0; nb < 8; nb++) {
            int nbg = colBase / 8 + nb;
            uint2 b = *(const uint2*)(g_Wf2p + (kc * 128 + nbg) * 64 + lane * 2);
            mma16816h(acc[nb], a, b.x, b.y);
        }
    }

#pragma unroll
    for (int nb = 0; nb < 8; nb++) {
        int c = colBase + nb * 8 + tid4 * 2;
        float2 bv = *(const float2*)(bf2 + c);
        if (r0 < NN) {
            float2 o = make_float2(fmaxf(acc[nb][0] + bv.x, 0.f),
                                   fmaxf(acc[nb][1] + bv.y, 0.f));
            *(float2*)(out + r0 * CIN + c) = o;
        }
        if (r1 < NN) {
            float2 o = make_float2(fmaxf(acc[nb][2] + bv.x, 0.f),
                                   fmaxf(acc[nb][3] + bv.y, 0.f));
            *(float2*)(out + r1 * CIN + c) = o;
        }
    }
}

// ---------------------------------------------------------------------------
extern "C" void kernel_launch(void* const* d_in, const int* in_sizes, int n_in,
                              void* d_out, int out_size) {
    const float* x    = (const float*)d_in[0];
    const void*  ei   = d_in[1];
    const float* Wg1  = (const float*)d_in[2];
    const float* bg1  = (const float*)d_in[3];
    const float* Wg2  = (const float*)d_in[4];
    const float* bg2  = (const float*)d_in[5];
    const float* Wf1  = (const float*)d_in[6];
    const float* bf1  = (const float*)d_in[7];
    const float* Wf2  = (const float*)d_in[8];
    const float* bf2  = (const float*)d_in[9];
    float* out = (float*)d_out;

    histprep_kernel<<<HISTB + PACKB, 256>>>(ei, Wg1, Wf2, Wg2, Wf1);  // 1
    alloc_kernel<<<NBLK, 256>>>();                                     // 2
    gemmscat_kernel<<<GEMMB + HISTB, 256>>>(x, ei);                    // 3
    gather1_kernel<<<(NN + 7) / 8, 256>>>(bg1);                        // 4 <- profiled

    t2_mma_kernel<<<(NN + 127) / 128, 256>>>();                        // 5
    gather2_kernel<<<(NN + 7) / 8, 256>>>(bg2);                        // 6
    z_mma_kernel<<<(NN + 127) / 128, 256>>>(bf1);                      // 7

    dim3 g2((NN + 63) / 64, CIN / 128);
    decode2_mma_kernel<<<g2, 256>>>(bf2, out);                         // 8
}

// round 15
// speedup vs baseline: 1.3043x; 1.0142x over previous
#include <cuda_runtime.h>
#include <cuda_fp16.h>

#define NN   100000
#define EE   1600000
#define CIN  1024
#define HD   64
#define ZDIM 32

#define NBLK ((NN + 255) / 256)    // 391
#define HISTB (EE / 256)           // 6250
#define PACKB 128                  // 32768 / 256
#define GEMMB ((NN + 127) / 128)   // 782

// ---------------- scratch (static __device__ — zero-initialized) ----------------
__device__ int   g_total;                 // reset by decode2 tail each run
__device__ int   g_deg[NN];               // re-zeroed by decode2 tail each run
__device__ int   g_off[NN];
__device__ int   g_cur[NN];
__device__ int   g_csr[EE];
__device__ float g_dinv[NN];
__device__ unsigned g_t1h[NN * 32 + 32];  // dinv-scaled x@Wg1, fp16 half2 (+zero pad row)
__device__ unsigned g_hh[NN * 32];        // encoder hidden h (post-relu), fp16 half2
__device__ unsigned g_t2h[NN * 16 + 16];  // dinv-scaled t2 = h@Wg2, fp16 half2 (+zero pad row)
__device__ unsigned g_zh[NN * 16];        // encoder output z, fp16 half2
__device__ unsigned g_dzp[NN * 32];       // decoder hidden, fp16 half2 words

__device__ __align__(16) unsigned g_Wg1p[64 * 8 * 64];     // 128 KB
__device__ __align__(16) unsigned g_Wf2p[4 * 128 * 64];    // 128 KB
__device__ __align__(16) unsigned g_Wg2p[4 * 4 * 64];      // 4 KB  (K=64, N=32)
__device__ __align__(16) unsigned g_Wf1p[2 * 8 * 64];      // 4 KB  (K=32, N=64)

// ---------------- helpers ----------------
__device__ __forceinline__ unsigned h2pack(float x0, float x1) {
    __half2 h = __float22half2_rn(make_float2(x0, x1));
    return *reinterpret_cast<unsigned*>(&h);
}
__device__ __forceinline__ float2 h2unpack(unsigned w) {
    return __half22float2(*reinterpret_cast<__half2*>(&w));
}
__device__ __forceinline__ unsigned hadd2u(unsigned a, unsigned b) {
    __half2 r = __hadd2(*reinterpret_cast<__half2*>(&a), *reinterpret_cast<__half2*>(&b));
    return *reinterpret_cast<unsigned*>(&r);
}

__device__ __forceinline__ void mma16816h(float* c, const unsigned* a, unsigned b0, unsigned b1) {
    asm volatile(
        "mma.sync.aligned.m16n8k16.row.col.f32.f16.f16.f32 "
        "{%0,%1,%2,%3}, {%4,%5,%6,%7}, {%8,%9}, {%0,%1,%2,%3};\n"
        : "+f"(c[0]), "+f"(c[1]), "+f"(c[2]), "+f"(c[3])
        : "r"(a[0]), "r"(a[1]), "r"(a[2]), "r"(a[3]), "r"(b0), "r"(b1));
}

__device__ __forceinline__ void cp16(unsigned smem_addr, const void* gptr) {
    asm volatile("cp.async.ca.shared.global [%0], [%1], 16;\n"
                 :: "r"(smem_addr), "l"(gptr));
}
__device__ __forceinline__ void cp_commit() { asm volatile("cp.async.commit_group;\n"); }
__device__ __forceinline__ void cp_wait1()  { asm volatile("cp.async.wait_group 1;\n" ::: "memory"); }

// per-block edge-dtype detection (int64 little-endian => odd 32-bit words all zero)
__device__ __forceinline__ int detect_is64_block(const int* ei32, int* s_flag) {
    if (threadIdx.x == 0) {
        int nz = 0;
#pragma unroll
        for (int k = 0; k < 16; k++) nz |= (ei32[2 * k + 1] != 0);
        *s_flag = nz ? 0 : 1;
    }
    __syncthreads();
    return *s_flag;
}

__device__ __forceinline__ void pack_one(const float* __restrict__ W, int K, int N,
                                         unsigned* __restrict__ pw, int idx) {
    int lane2 = idx & 63;
    int j = lane2 & 1;
    int lane = lane2 >> 1;
    int nb = (idx >> 6) % (N / 8);
    int kc = idx / (64 * (N / 8));
    int k0 = kc * 16 + (lane & 3) * 2 + j * 8;
    int n = nb * 8 + (lane >> 2);
    pw[idx] = h2pack(W[(long long)k0 * N + n], W[(long long)(k0 + 1) * N + n]);
}

// ---------------- launch 1: hist + weight packing ----------------
__global__ void histprep_kernel(const void* __restrict__ ei,
                                const float* __restrict__ Wg1,
                                const float* __restrict__ Wf2,
                                const float* __restrict__ Wg2,
                                const float* __restrict__ Wf1) {
    __shared__ int s_is64;
    int b = blockIdx.x;
    if (b < HISTB) {
        int is64 = detect_is64_block((const int*)ei, &s_is64);
        int e = b * 256 + threadIdx.x;
        int d = is64 ? (int)((const long long*)ei)[EE + e]
                     : ((const int*)ei)[EE + e];
        atomicAdd(&g_deg[d], 1);
    } else {
        int idx = (b - HISTB) * 256 + threadIdx.x;   // 0..32767
        pack_one(Wg1, CIN, HD, g_Wg1p, idx);
        pack_one(Wf2, HD, CIN, g_Wf2p, idx);
        if (idx < 4 * 4 * 64) pack_one(Wg2, HD, ZDIM, g_Wg2p, idx);
        if (idx < 2 * 8 * 64) pack_one(Wf1, ZDIM, HD, g_Wf1p, idx);
    }
}

// ---------------- launch 2: alloc ----------------
__global__ void alloc_kernel() {
    int i = blockIdx.x * blockDim.x + threadIdx.x;
    int lane = threadIdx.x & 31;
    int d = (i < NN) ? g_deg[i] : 0;
    int p = d;
#pragma unroll
    for (int o = 1; o < 32; o <<= 1) {
        int t = __shfl_up_sync(0xffffffffu, p, o);
        if (lane >= o) p += t;
    }
    int tot = __shfl_sync(0xffffffffu, p, 31);
    int base = 0;
    if (lane == 31) base = atomicAdd(&g_total, tot);
    base = __shfl_sync(0xffffffffu, base, 31);
    if (i < NN) {
        int off = base + p - d;
        g_off[i] = off;
        g_cur[i] = off;
        g_dinv[i] = rsqrtf((float)(d + 1));
    }
}

// ---------------- launch 3: gemm1 + scatter (fused) ----------------
__global__ __launch_bounds__(256, 3) void gemmscat_kernel(const float* __restrict__ x,
                                                          const void* __restrict__ ei) {
    __shared__ __align__(16) unsigned Bs[3 * 512];
    __shared__ int s_is64;
    int tid = threadIdx.x;

    if (blockIdx.x >= GEMMB) {
        int is64 = detect_is64_block((const int*)ei, &s_is64);
        int e = (blockIdx.x - GEMMB) * 256 + tid;
        int s, d;
        if (is64) {
            s = (int)((const long long*)ei)[e];
            d = (int)((const long long*)ei)[EE + e];
        } else {
            s = ((const int*)ei)[e];
            d = ((const int*)ei)[EE + e];
        }
        int pos = atomicAdd(&g_cur[d], 1);
        g_csr[pos] = s;
        return;
    }

    int wid = tid >> 5, lane = tid & 31;
    int gid = lane >> 2, tid4 = lane & 3;
    long long rowBase = (long long)blockIdx.x * 128 + wid * 16;

    long long r0 = rowBase + gid;
    long long r1 = r0 + 8;
    long long c0 = (r0 < NN) ? r0 : NN - 1;
    long long c1 = (r1 < NN) ? r1 : NN - 1;
    const float* p0 = x + c0 * CIN;
    const float* p1 = x + c1 * CIN;

    unsigned sbase = (unsigned)__cvta_generic_to_shared(Bs);
    int doCp = (tid < 128);

    if (doCp) cp16(sbase + tid * 16, g_Wg1p + tid * 4);
    cp_commit();
    if (doCp) cp16(sbase + 512 * 4 + tid * 16, g_Wg1p + 512 + tid * 4);
    cp_commit();

    float acc[8][4];
#pragma unroll
    for (int nb = 0; nb < 8; nb++)
#pragma unroll
        for (int q = 0; q < 4; q++) acc[nb][q] = 0.f;

    float2 a0, a1, a2, a3;
    {
        int col = tid4 * 2;
        a0 = *(const float2*)(p0 + col);
        a1 = *(const float2*)(p1 + col);
        a2 = *(const float2*)(p0 + col + 8);
        a3 = *(const float2*)(p1 + col + 8);
    }

    for (int kc = 0; kc < 64; kc++) {
        float2 n0, n1, n2, n3;
        if (kc < 63) {
            int col = (kc + 1) * 16 + tid4 * 2;
            n0 = *(const float2*)(p0 + col);
            n1 = *(const float2*)(p1 + col);
            n2 = *(const float2*)(p0 + col + 8);
            n3 = *(const float2*)(p1 + col + 8);
        }

        cp_wait1();
        __syncthreads();
        if (kc + 2 < 64 && doCp)
            cp16(sbase + ((kc + 2) % 3) * 512 * 4 + tid * 16, g_Wg1p + (kc + 2) * 512 + tid * 4);
        cp_commit();

        unsigned at[4];
        at[0] = h2pack(a0.x, a0.y);
        at[1] = h2pack(a1.x, a1.y);
        at[2] = h2pack(a2.x, a2.y);
        at[3] = h2pack(a3.x, a3.y);

        const unsigned* BsS = Bs + (kc % 3) * 512;
#pragma unroll
        for (int nb = 0; nb < 8; nb++) {
            uint2 b = *(const uint2*)(BsS + nb * 64 + lane * 2);
            mma16816h(acc[nb], at, b.x, b.y);
        }
        a0 = n0; a1 = n1; a2 = n2; a3 = n3;
    }

    float di0 = (r0 < NN) ? g_dinv[r0] : 0.f;
    float di1 = (r1 < NN) ? g_dinv[r1] : 0.f;
#pragma unroll
    for (int nb = 0; nb < 8; nb++) {
        int w = nb * 4 + tid4;
        if (r0 < NN) g_t1h[r0 * 32 + w] = h2pack(acc[nb][0] * di0, acc[nb][1] * di0);
        if (r1 < NN) g_t1h[r1 * 32 + w] = h2pack(acc[nb][2] * di1, acc[nb][3] * di1);
    }
}

// ------- launch 4 (profiled): gather1 — HADD2 aggregation + relu -------
__global__ __launch_bounds__(256) void gather1_kernel(const float* __restrict__ bg1) {
    __shared__ float bg1s[HD];
    int tid = threadIdx.x;
    if (tid < HD) bg1s[tid] = bg1[tid];
    __syncthreads();

    int v = blockIdx.x * 8 + (tid >> 5);
    if (v >= NN) return;
    int lane = tid & 31;

    float a0 = 0.f, a1 = 0.f;           // fp32 totals
    int beg = g_off[v];
    int cnt = g_deg[v];
    for (int base = 0; base < cnt; base += 32) {
        int j = base + lane;
        int soff = (j < cnt) ? g_csr[beg + j] * 32 : NN * 32;
        int rem = cnt - base;
        if (rem > 32) rem = 32;
#pragma unroll
        for (int qq = 0; qq < 4; qq++) {
            if (qq * 8 >= rem) break;
            unsigned hA = 0, hB = 0;    // fp16 half2 accumulators (chains <= 4 adds)
#pragma unroll
            for (int qi = 0; qi < 8; qi++) {
                int ov = __shfl_sync(0xffffffffu, soff, qq * 8 + qi);
                unsigned fv = g_t1h[ov + lane];
                if (qi & 1) hB = hadd2u(hB, fv);
                else        hA = hadd2u(hA, fv);
            }
            float2 fA = h2unpack(hA);
            float2 fB = h2unpack(hB);
            a0 += fA.x + fB.x;
            a1 += fA.y + fB.y;
        }
    }
    float di = g_dinv[v];
    float2 pv = h2unpack(g_t1h[(long long)v * 32 + lane]);
    float h0 = fmaxf(di * (a0 + pv.x) + bg1s[2 * lane],     0.f);
    float h1 = fmaxf(di * (a1 + pv.y) + bg1s[2 * lane + 1], 0.f);
    g_hh[(long long)v * 32 + lane] = h2pack(h0, h1);
}

// ---- launch 5: t2 MMA — t2h = dinv .* (h[N,64] @ Wg2[64,32]) ----
__global__ __launch_bounds__(256, 3) void t2_mma_kernel() {
    int tid = threadIdx.x;
    int wid = tid >> 5, lane = tid & 31;
    int gid = lane >> 2, tid4 = lane & 3;
    long long rowBase = (long long)blockIdx.x * 128 + wid * 16;

    long long r0 = rowBase + gid;
    long long r1 = r0 + 8;
    long long c0 = (r0 < NN) ? r0 : NN - 1;
    long long c1 = (r1 < NN) ? r1 : NN - 1;
    long long rp0 = c0 * 32, rp1 = c1 * 32;

    float acc[4][4];
#pragma unroll
    for (int nb = 0; nb < 4; nb++)
#pragma unroll
        for (int q = 0; q < 4; q++) acc[nb][q] = 0.f;

#pragma unroll
    for (int kc = 0; kc < 4; kc++) {
        unsigned a[4];
        a[0] = g_hh[rp0 + kc * 8 + tid4];
        a[1] = g_hh[rp1 + kc * 8 + tid4];
        a[2] = g_hh[rp0 + kc * 8 + tid4 + 4];
        a[3] = g_hh[rp1 + kc * 8 + tid4 + 4];
#pragma unroll
        for (int nb = 0; nb < 4; nb++) {
            uint2 b = *(const uint2*)(g_Wg2p + (kc * 4 + nb) * 64 + lane * 2);
            mma16816h(acc[nb], a, b.x, b.y);
        }
    }

    float di0 = (r0 < NN) ? g_dinv[r0] : 0.f;
    float di1 = (r1 < NN) ? g_dinv[r1] : 0.f;
#pragma unroll
    for (int nb = 0; nb < 4; nb++) {
        int w = nb * 4 + tid4;
        if (r0 < NN) g_t2h[r0 * 16 + w] = h2pack(acc[nb][0] * di0, acc[nb][1] * di0);
        if (r1 < NN) g_t2h[r1 * 16 + w] = h2pack(acc[nb][2] * di1, acc[nb][3] * di1);
    }
}

// -- launch 6: gather2 — HADD2 aggregation; z stored fp16 --
__global__ __launch_bounds__(256) void gather2_kernel(const float* __restrict__ bg2) {
    __shared__ float bg2s[ZDIM];
    int tid = threadIdx.x;
    if (tid < ZDIM) bg2s[tid] = bg2[tid];
    __syncthreads();

    int v = blockIdx.x * 8 + (tid >> 5);
    if (v >= NN) return;
    int lane = tid & 31;
    int lp = lane & 15;

    float a0 = 0.f, a1 = 0.f;
    int beg = g_off[v];
    int cnt = g_deg[v];
    for (int base = 0; base < cnt; base += 32) {
        int j = base + lane;
        int soff = (j < cnt) ? g_csr[beg + j] * 16 : NN * 16;
        int rem = cnt - base;
        if (rem > 32) rem = 32;
#pragma unroll
        for (int qq = 0; qq < 4; qq++) {
            if (qq * 8 >= rem) break;
            unsigned hA = 0, hB = 0;
#pragma unroll
            for (int qi = 0; qi < 8; qi++) {
                int ov = __shfl_sync(0xffffffffu, soff, qq * 8 + qi);
                unsigned fv = g_t2h[ov + lp];
                if (qi & 1) hB = hadd2u(hB, fv);
                else        hA = hadd2u(hA, fv);
            }
            float2 fA = h2unpack(hA);
            float2 fB = h2unpack(hB);
            a0 += fA.x + fB.x;
            a1 += fA.y + fB.y;
        }
    }
    float di = g_dinv[v];
    float2 pv = h2unpack(g_t2h[(long long)v * 16 + lp]);
    float z0 = di * (a0 + pv.x) + bg2s[2 * lp];
    float z1 = di * (a1 + pv.y) + bg2s[2 * lp + 1];
    if (lane < 16)
        g_zh[(long long)v * 16 + lp] = h2pack(z0, z1);
}

// ---- launch 7: z MMA — dzp = relu(z[N,32] @ Wf1[32,64] + bf1) ----
__global__ __launch_bounds__(256, 3) void z_mma_kernel(const float* __restrict__ bf1) {
    __shared__ float bf1s[HD];
    int tid = threadIdx.x;
    if (tid < HD) bf1s[tid] = bf1[tid];
    __syncthreads();

    int wid = tid >> 5, lane = tid & 31;
    int gid = lane >> 2, tid4 = lane & 3;
    long long rowBase = (long long)blockIdx.x * 128 + wid * 16;

    long long r0 = rowBase + gid;
    long long r1 = r0 + 8;
    long long c0 = (r0 < NN) ? r0 : NN - 1;
    long long c1 = (r1 < NN) ? r1 : NN - 1;
    long long rp0 = c0 * 16, rp1 = c1 * 16;

    float acc[8][4];
#pragma unroll
    for (int nb = 0; nb < 8; nb++)
#pragma unroll
        for (int q = 0; q < 4; q++) acc[nb][q] = 0.f;

#pragma unroll
    for (int kc = 0; kc < 2; kc++) {
        unsigned a[4];
        a[0] = g_zh[rp0 + kc * 8 + tid4];
        a[1] = g_zh[rp1 + kc * 8 + tid4];
        a[2] = g_zh[rp0 + kc * 8 + tid4 + 4];
        a[3] = g_zh[rp1 + kc * 8 + tid4 + 4];
#pragma unroll
        for (int nb = 0; nb < 8; nb++) {
            uint2 b = *(const uint2*)(g_Wf1p + (kc * 8 + nb) * 64 + lane * 2);
            mma16816h(acc[nb], a, b.x, b.y);
        }
    }

#pragma unroll
    for (int nb = 0; nb < 8; nb++) {
        int c = nb * 8 + tid4 * 2;
        float b0 = bf1s[c], b1 = bf1s[c + 1];
        int w = nb * 4 + tid4;
        if (r0 < NN)
            g_dzp[r0 * 32 + w] = h2pack(fmaxf(acc[nb][0] + b0, 0.f), fmaxf(acc[nb][1] + b1, 0.f));
        if (r1 < NN)
            g_dzp[r1 * 32 + w] = h2pack(fmaxf(acc[nb][2] + b0, 0.f), fmaxf(acc[nb][3] + b1, 0.f));
    }
}

// ---- launch 8: decode2 + tail cleanup ----
__global__ __launch_bounds__(256, 3) void decode2_mma_kernel(const float* __restrict__ bf2,
                                                             float* __restrict__ out) {
    int tid = threadIdx.x;

    if (blockIdx.y == 0) {
        int i = blockIdx.x * 256 + tid;
        if (i < NN) g_deg[i] = 0;
        if (i == 0) g_total = 0;
    }

    int wid = tid >> 5, lane = tid & 31;
    int gid = lane >> 2, tid4 = lane & 3;
    int warpM = wid & 3, warpN = wid >> 2;
    long long rowBase = (long long)blockIdx.x * 64 + warpM * 16;
    int colBase = blockIdx.y * 128 + warpN * 64;

    long long r0 = rowBase + gid;
    long long r1 = r0 + 8;
    long long c0 = (r0 < NN) ? r0 : NN - 1;
    long long c1 = (r1 < NN) ? r1 : NN - 1;
    long long rp0 = c0 * 32, rp1 = c1 * 32;

    float acc[8][4];
#pragma unroll
    for (int nb = 0; nb < 8; nb++)
#pragma unroll
        for (int q = 0; q < 4; q++) acc[nb][q] = 0.f;

#pragma unroll
    for (int kc = 0; kc < 4; kc++) {
        unsigned a[4];
        a[0] = g_dzp[rp0 + kc * 8 + tid4];
        a[1] = g_dzp[rp1 + kc * 8 + tid4];
        a[2] = g_dzp[rp0 + kc * 8 + tid4 + 4];
        a[3] = g_dzp[rp1 + kc * 8 + tid4 + 4];
#pragma unroll
        for (int nb = 0; nb < 8; nb++) {
            int nbg = colBase / 8 + nb;
            uint2 b = *(const uint2*)(g_Wf2p + (kc * 128 + nbg) * 64 + lane * 2);
            mma16816h(acc[nb], a, b.x, b.y);
        }
    }

#pragma unroll
    for (int nb = 0; nb < 8; nb++) {
        int c = colBase + nb * 8 + tid4 * 2;
        float2 bv = *(const float2*)(bf2 + c);
        if (r0 < NN) {
            float2 o = make_float2(fmaxf(acc[nb][0] + bv.x, 0.f),
                                   fmaxf(acc[nb][1] + bv.y, 0.f));
            *(float2*)(out + r0 * CIN + c) = o;
        }
        if (r1 < NN) {
            float2 o = make_float2(fmaxf(acc[nb][2] + bv.x, 0.f),
                                   fmaxf(acc[nb][3] + bv.y, 0.f));
            *(float2*)(out + r1 * CIN + c) = o;
        }
    }
}

// ---------------------------------------------------------------------------
extern "C" void kernel_launch(void* const* d_in, const int* in_sizes, int n_in,
                              void* d_out, int out_size) {
    const float* x    = (const float*)d_in[0];
    const void*  ei   = d_in[1];
    const float* Wg1  = (const float*)d_in[2];
    const float* bg1  = (const float*)d_in[3];
    const float* Wg2  = (const float*)d_in[4];
    const float* bg2  = (const float*)d_in[5];
    const float* Wf1  = (const float*)d_in[6];
    const float* bf1  = (const float*)d_in[7];
    const float* Wf2  = (const float*)d_in[8];
    const float* bf2  = (const float*)d_in[9];
    float* out = (float*)d_out;

    histprep_kernel<<<HISTB + PACKB, 256>>>(ei, Wg1, Wf2, Wg2, Wf1);  // 1
    alloc_kernel<<<NBLK, 256>>>();                                     // 2
    gemmscat_kernel<<<GEMMB + HISTB, 256>>>(x, ei);                    // 3
    gather1_kernel<<<(NN + 7) / 8, 256>>>(bg1);                        // 4 <- profiled

    t2_mma_kernel<<<(NN + 127) / 128, 256>>>();                        // 5
    gather2_kernel<<<(NN + 7) / 8, 256>>>(bg2);                        // 6
    z_mma_kernel<<<(NN + 127) / 128, 256>>>(bf1);                      // 7

    dim3 g2((NN + 63) / 64, CIN / 128);
    decode2_mma_kernel<<<g2, 256>>>(bf2, out);                         // 8
}

// round 16
// speedup vs baseline: 1.5584x; 1.1948x over previous
#include <cuda_runtime.h>
#include <cuda_fp16.h>

#define NN   100000
#define EE   1600000
#define CIN  1024
#define HD   64
#define ZDIM 32

#define NBLK ((NN + 255) / 256)    // 391
#define HISTB (EE / 256)           // 6250
#define PACKB 128                  // 32768 / 256
#define GEMMB ((NN + 127) / 128)   // 782

// ---------------- scratch (static __device__ — zero-initialized) ----------------
__device__ int   g_total;                 // reset by decode2 tail each run
__device__ int   g_deg[NN];               // re-zeroed by decode2 tail each run
__device__ int   g_off[NN];
__device__ int   g_cur[NN];
__device__ int   g_csr[EE];
__device__ float g_dinv[NN];
__device__ unsigned g_t1h[NN * 32 + 32];  // dinv-scaled x@Wg1, fp16 half2 (+zero pad row)
__device__ unsigned g_hh[NN * 32];        // encoder hidden h (post-relu), fp16 half2
__device__ unsigned g_t2h[NN * 16 + 16];  // dinv-scaled t2 = h@Wg2, fp16 half2 (+zero pad row)
__device__ unsigned g_zh[NN * 16];        // encoder output z, fp16 half2
__device__ unsigned g_dzp[NN * 32];       // decoder hidden, fp16 half2 words

// K-PERMUTED frag-packed weights: within each 16-k chunk, lane t (= lane&3) owns
// physical k {4t, 4t+1, 4t+2, 4t+3}; j=0 -> (4t, 4t+1), j=1 -> (4t+2, 4t+3).
// A-operands must use the same permutation (frag a[0]/a[2] = phys pairs).
__device__ __align__(16) unsigned g_Wg1p[64 * 8 * 64];     // 128 KB
__device__ __align__(16) unsigned g_Wf2p[4 * 128 * 64];    // 128 KB
__device__ __align__(16) unsigned g_Wg2p[4 * 4 * 64];      // 4 KB
__device__ __align__(16) unsigned g_Wf1p[2 * 8 * 64];      // 4 KB

// ---------------- helpers ----------------
__device__ __forceinline__ unsigned h2pack(float x0, float x1) {
    __half2 h = __float22half2_rn(make_float2(x0, x1));
    return *reinterpret_cast<unsigned*>(&h);
}
__device__ __forceinline__ float2 h2unpack(unsigned w) {
    return __half22float2(*reinterpret_cast<__half2*>(&w));
}
__device__ __forceinline__ unsigned hadd2u(unsigned a, unsigned b) {
    __half2 r = __hadd2(*reinterpret_cast<__half2*>(&a), *reinterpret_cast<__half2*>(&b));
    return *reinterpret_cast<unsigned*>(&r);
}

__device__ __forceinline__ void mma16816h(float* c, const unsigned* a, unsigned b0, unsigned b1) {
    asm volatile(
        "mma.sync.aligned.m16n8k16.row.col.f32.f16.f16.f32 "
        "{%0,%1,%2,%3}, {%4,%5,%6,%7}, {%8,%9}, {%0,%1,%2,%3};\n"
        : "+f"(c[0]), "+f"(c[1]), "+f"(c[2]), "+f"(c[3])
        : "r"(a[0]), "r"(a[1]), "r"(a[2]), "r"(a[3]), "r"(b0), "r"(b1));
}

__device__ __forceinline__ void cp16(unsigned smem_addr, const void* gptr) {
    asm volatile("cp.async.ca.shared.global [%0], [%1], 16;\n"
                 :: "r"(smem_addr), "l"(gptr));
}
__device__ __forceinline__ void cp_commit() { asm volatile("cp.async.commit_group;\n"); }
__device__ __forceinline__ void cp_wait1()  { asm volatile("cp.async.wait_group 1;\n" ::: "memory"); }

__device__ __forceinline__ int detect_is64_block(const int* ei32, int* s_flag) {
    if (threadIdx.x == 0) {
        int nz = 0;
#pragma unroll
        for (int k = 0; k < 16; k++) nz |= (ei32[2 * k + 1] != 0);
        *s_flag = nz ? 0 : 1;
    }
    __syncthreads();
    return *s_flag;
}

// K-permuted pack: frag j-pair (j=0,1) <- physical k = kc*16 + (lane&3)*4 + j*2
__device__ __forceinline__ void pack_one(const float* __restrict__ W, int K, int N,
                                         unsigned* __restrict__ pw, int idx) {
    int lane2 = idx & 63;
    int j = lane2 & 1;
    int lane = lane2 >> 1;
    int nb = (idx >> 6) % (N / 8);
    int kc = idx / (64 * (N / 8));
    int k0 = kc * 16 + (lane & 3) * 4 + j * 2;
    int n = nb * 8 + (lane >> 2);
    pw[idx] = h2pack(W[(long long)k0 * N + n], W[(long long)(k0 + 1) * N + n]);
}

// ---------------- launch 1: hist + weight packing ----------------
__global__ void histprep_kernel(const void* __restrict__ ei,
                                const float* __restrict__ Wg1,
                                const float* __restrict__ Wf2,
                                const float* __restrict__ Wg2,
                                const float* __restrict__ Wf1) {
    __shared__ int s_is64;
    int b = blockIdx.x;
    if (b < HISTB) {
        int is64 = detect_is64_block((const int*)ei, &s_is64);
        int e = b * 256 + threadIdx.x;
        int d = is64 ? (int)((const long long*)ei)[EE + e]
                     : ((const int*)ei)[EE + e];
        atomicAdd(&g_deg[d], 1);
    } else {
        int idx = (b - HISTB) * 256 + threadIdx.x;   // 0..32767
        pack_one(Wg1, CIN, HD, g_Wg1p, idx);
        pack_one(Wf2, HD, CIN, g_Wf2p, idx);
        if (idx < 4 * 4 * 64) pack_one(Wg2, HD, ZDIM, g_Wg2p, idx);
        if (idx < 2 * 8 * 64) pack_one(Wf1, ZDIM, HD, g_Wf1p, idx);
    }
}

// ---------------- launch 2: alloc ----------------
__global__ void alloc_kernel() {
    int i = blockIdx.x * blockDim.x + threadIdx.x;
    int lane = threadIdx.x & 31;
    int d = (i < NN) ? g_deg[i] : 0;
    int p = d;
#pragma unroll
    for (int o = 1; o < 32; o <<= 1) {
        int t = __shfl_up_sync(0xffffffffu, p, o);
        if (lane >= o) p += t;
    }
    int tot = __shfl_sync(0xffffffffu, p, 31);
    int base = 0;
    if (lane == 31) base = atomicAdd(&g_total, tot);
    base = __shfl_sync(0xffffffffu, base, 31);
    if (i < NN) {
        int off = base + p - d;
        g_off[i] = off;
        g_cur[i] = off;
        g_dinv[i] = rsqrtf((float)(d + 1));
    }
}

// ---------------- launch 3: gemm1 + scatter (fused) ----------------
__global__ __launch_bounds__(256, 3) void gemmscat_kernel(const float* __restrict__ x,
                                                          const void* __restrict__ ei) {
    __shared__ __align__(16) unsigned Bs[3 * 512];
    __shared__ int s_is64;
    int tid = threadIdx.x;

    if (blockIdx.x >= GEMMB) {
        int is64 = detect_is64_block((const int*)ei, &s_is64);
        int e = (blockIdx.x - GEMMB) * 256 + tid;
        int s, d;
        if (is64) {
            s = (int)((const long long*)ei)[e];
            d = (int)((const long long*)ei)[EE + e];
        } else {
            s = ((const int*)ei)[e];
            d = ((const int*)ei)[EE + e];
        }
        int pos = atomicAdd(&g_cur[d], 1);
        g_csr[pos] = s;
        return;
    }

    int wid = tid >> 5, lane = tid & 31;
    int gid = lane >> 2, tid4 = lane & 3;
    long long rowBase = (long long)blockIdx.x * 128 + wid * 16;

    long long r0 = rowBase + gid;
    long long r1 = r0 + 8;
    long long c0 = (r0 < NN) ? r0 : NN - 1;
    long long c1 = (r1 < NN) ? r1 : NN - 1;
    const float* p0 = x + c0 * CIN;
    const float* p1 = x + c1 * CIN;

    unsigned sbase = (unsigned)__cvta_generic_to_shared(Bs);
    int doCp = (tid < 128);

    if (doCp) cp16(sbase + tid * 16, g_Wg1p + tid * 4);
    cp_commit();
    if (doCp) cp16(sbase + 512 * 4 + tid * 16, g_Wg1p + 512 + tid * 4);
    cp_commit();

    float acc[8][4];
#pragma unroll
    for (int nb = 0; nb < 8; nb++)
#pragma unroll
        for (int q = 0; q < 4; q++) acc[nb][q] = 0.f;

    // K-permuted A: lane owns phys cols {4t..4t+3} of each 16-chunk -> one float4/row
    float4 a0, a1;
    {
        int col = tid4 * 4;
        a0 = __ldcs((const float4*)(p0 + col));
        a1 = __ldcs((const float4*)(p1 + col));
    }

    for (int kc = 0; kc < 64; kc++) {
        float4 n0, n1;
        if (kc < 63) {
            int col = (kc + 1) * 16 + tid4 * 4;
            n0 = __ldcs((const float4*)(p0 + col));
            n1 = __ldcs((const float4*)(p1 + col));
        }

        cp_wait1();
        __syncthreads();
        if (kc + 2 < 64 && doCp)
            cp16(sbase + ((kc + 2) % 3) * 512 * 4 + tid * 16, g_Wg1p + (kc + 2) * 512 + tid * 4);
        cp_commit();

        unsigned at[4];
        at[0] = h2pack(a0.x, a0.y);
        at[1] = h2pack(a1.x, a1.y);
        at[2] = h2pack(a0.z, a0.w);
        at[3] = h2pack(a1.z, a1.w);

        const unsigned* BsS = Bs + (kc % 3) * 512;
#pragma unroll
        for (int nb = 0; nb < 8; nb++) {
            uint2 b = *(const uint2*)(BsS + nb * 64 + lane * 2);
            mma16816h(acc[nb], at, b.x, b.y);
        }
        a0 = n0; a1 = n1;
    }

    float di0 = (r0 < NN) ? g_dinv[r0] : 0.f;
    float di1 = (r1 < NN) ? g_dinv[r1] : 0.f;
#pragma unroll
    for (int nb = 0; nb < 8; nb++) {
        int w = nb * 4 + tid4;
        if (r0 < NN) g_t1h[r0 * 32 + w] = h2pack(acc[nb][0] * di0, acc[nb][1] * di0);
        if (r1 < NN) g_t1h[r1 * 32 + w] = h2pack(acc[nb][2] * di1, acc[nb][3] * di1);
    }
}

// ------- launch 4 (profiled): gather1 — HADD2 aggregation + relu -------
__global__ __launch_bounds__(256) void gather1_kernel(const float* __restrict__ bg1) {
    __shared__ float bg1s[HD];
    int tid = threadIdx.x;
    if (tid < HD) bg1s[tid] = bg1[tid];
    __syncthreads();

    int v = blockIdx.x * 8 + (tid >> 5);
    if (v >= NN) return;
    int lane = tid & 31;

    float a0 = 0.f, a1 = 0.f;
    int beg = g_off[v];
    int cnt = g_deg[v];
    for (int base = 0; base < cnt; base += 32) {
        int j = base + lane;
        int soff = (j < cnt) ? g_csr[beg + j] * 32 : NN * 32;
        int rem = cnt - base;
        if (rem > 32) rem = 32;
#pragma unroll
        for (int qq = 0; qq < 4; qq++) {
            if (qq * 8 >= rem) break;
            unsigned hA = 0, hB = 0;
#pragma unroll
            for (int qi = 0; qi < 8; qi++) {
                int ov = __shfl_sync(0xffffffffu, soff, qq * 8 + qi);
                unsigned fv = g_t1h[ov + lane];
                if (qi & 1) hB = hadd2u(hB, fv);
                else        hA = hadd2u(hA, fv);
            }
            float2 fA = h2unpack(hA);
            float2 fB = h2unpack(hB);
            a0 += fA.x + fB.x;
            a1 += fA.y + fB.y;
        }
    }
    float di = g_dinv[v];
    float2 pv = h2unpack(g_t1h[(long long)v * 32 + lane]);
    float h0 = fmaxf(di * (a0 + pv.x) + bg1s[2 * lane],     0.f);
    float h1 = fmaxf(di * (a1 + pv.y) + bg1s[2 * lane + 1], 0.f);
    g_hh[(long long)v * 32 + lane] = h2pack(h0, h1);
}

// ---- launch 5: t2 MMA — t2h = dinv .* (h[N,64] @ Wg2[64,32]) ----
__global__ __launch_bounds__(256, 3) void t2_mma_kernel() {
    int tid = threadIdx.x;
    int wid = tid >> 5, lane = tid & 31;
    int gid = lane >> 2, tid4 = lane & 3;
    long long rowBase = (long long)blockIdx.x * 128 + wid * 16;

    long long r0 = rowBase + gid;
    long long r1 = r0 + 8;
    long long c0 = (r0 < NN) ? r0 : NN - 1;
    long long c1 = (r1 < NN) ? r1 : NN - 1;
    long long rp0 = c0 * 32, rp1 = c1 * 32;

    float acc[4][4];
#pragma unroll
    for (int nb = 0; nb < 4; nb++)
#pragma unroll
        for (int q = 0; q < 4; q++) acc[nb][q] = 0.f;

#pragma unroll
    for (int kc = 0; kc < 4; kc++) {
        // K-permuted A frag: contiguous word pair per row
        uint2 u0 = *(const uint2*)(g_hh + rp0 + kc * 8 + tid4 * 2);
        uint2 u1 = *(const uint2*)(g_hh + rp1 + kc * 8 + tid4 * 2);
        unsigned a[4] = { u0.x, u1.x, u0.y, u1.y };
#pragma unroll
        for (int nb = 0; nb < 4; nb++) {
            uint2 b = *(const uint2*)(g_Wg2p + (kc * 4 + nb) * 64 + lane * 2);
            mma16816h(acc[nb], a, b.x, b.y);
        }
    }

    float di0 = (r0 < NN) ? g_dinv[r0] : 0.f;
    float di1 = (r1 < NN) ? g_dinv[r1] : 0.f;
#pragma unroll
    for (int nb = 0; nb < 4; nb++) {
        int w = nb * 4 + tid4;
        if (r0 < NN) g_t2h[r0 * 16 + w] = h2pack(acc[nb][0] * di0, acc[nb][1] * di0);
        if (r1 < NN) g_t2h[r1 * 16 + w] = h2pack(acc[nb][2] * di1, acc[nb][3] * di1);
    }
}

// -- launch 6: gather2 — HADD2 aggregation; z stored fp16 --
__global__ __launch_bounds__(256) void gather2_kernel(const float* __restrict__ bg2) {
    __shared__ float bg2s[ZDIM];
    int tid = threadIdx.x;
    if (tid < ZDIM) bg2s[tid] = bg2[tid];
    __syncthreads();

    int v = blockIdx.x * 8 + (tid >> 5);
    if (v >= NN) return;
    int lane = tid & 31;
    int lp = lane & 15;

    float a0 = 0.f, a1 = 0.f;
    int beg = g_off[v];
    int cnt = g_deg[v];
    for (int base = 0; base < cnt; base += 32) {
        int j = base + lane;
        int soff = (j < cnt) ? g_csr[beg + j] * 16 : NN * 16;
        int rem = cnt - base;
        if (rem > 32) rem = 32;
#pragma unroll
        for (int qq = 0; qq < 4; qq++) {
            if (qq * 8 >= rem) break;
            unsigned hA = 0, hB = 0;
#pragma unroll
            for (int qi = 0; qi < 8; qi++) {
                int ov = __shfl_sync(0xffffffffu, soff, qq * 8 + qi);
                unsigned fv = g_t2h[ov + lp];
                if (qi & 1) hB = hadd2u(hB, fv);
                else        hA = hadd2u(hA, fv);
            }
            float2 fA = h2unpack(hA);
            float2 fB = h2unpack(hB);
            a0 += fA.x + fB.x;
            a1 += fA.y + fB.y;
        }
    }
    float di = g_dinv[v];
    float2 pv = h2unpack(g_t2h[(long long)v * 16 + lp]);
    float z0 = di * (a0 + pv.x) + bg2s[2 * lp];
    float z1 = di * (a1 + pv.y) + bg2s[2 * lp + 1];
    if (lane < 16)
        g_zh[(long long)v * 16 + lp] = h2pack(z0, z1);
}

// ---- launch 7: z MMA — dzp = relu(z[N,32] @ Wf1[32,64] + bf1) ----
__global__ __launch_bounds__(256, 3) void z_mma_kernel(const float* __restrict__ bf1) {
    __shared__ float bf1s[HD];
    int tid = threadIdx.x;
    if (tid < HD) bf1s[tid] = bf1[tid];
    __syncthreads();

    int wid = tid >> 5, lane = tid & 31;
    int gid = lane >> 2, tid4 = lane & 3;
    long long rowBase = (long long)blockIdx.x * 128 + wid * 16;

    long long r0 = rowBase + gid;
    long long r1 = r0 + 8;
    long long c0 = (r0 < NN) ? r0 : NN - 1;
    long long c1 = (r1 < NN) ? r1 : NN - 1;
    long long rp0 = c0 * 16, rp1 = c1 * 16;

    float acc[8][4];
#pragma unroll
    for (int nb = 0; nb < 8; nb++)
#pragma unroll
        for (int q = 0; q < 4; q++) acc[nb][q] = 0.f;

#pragma unroll
    for (int kc = 0; kc < 2; kc++) {
        uint2 u0 = *(const uint2*)(g_zh + rp0 + kc * 8 + tid4 * 2);
        uint2 u1 = *(const uint2*)(g_zh + rp1 + kc * 8 + tid4 * 2);
        unsigned a[4] = { u0.x, u1.x, u0.y, u1.y };
#pragma unroll
        for (int nb = 0; nb < 8; nb++) {
            uint2 b = *(const uint2*)(g_Wf1p + (kc * 8 + nb) * 64 + lane * 2);
            mma16816h(acc[nb], a, b.x, b.y);
        }
    }

#pragma unroll
    for (int nb = 0; nb < 8; nb++) {
        int c = nb * 8 + tid4 * 2;
        float b0 = bf1s[c], b1 = bf1s[c + 1];
        int w = nb * 4 + tid4;
        if (r0 < NN)
            g_dzp[r0 * 32 + w] = h2pack(fmaxf(acc[nb][0] + b0, 0.f), fmaxf(acc[nb][1] + b1, 0.f));
        if (r1 < NN)
            g_dzp[r1 * 32 + w] = h2pack(fmaxf(acc[nb][2] + b0, 0.f), fmaxf(acc[nb][3] + b1, 0.f));
    }
}

// ---- launch 8: decode2 + tail cleanup ----
__global__ __launch_bounds__(256, 3) void decode2_mma_kernel(const float* __restrict__ bf2,
                                                             float* __restrict__ out) {
    int tid = threadIdx.x;

    if (blockIdx.y == 0) {
        int i = blockIdx.x * 256 + tid;
        if (i < NN) g_deg[i] = 0;
        if (i == 0) g_total = 0;
    }

    int wid = tid >> 5, lane = tid & 31;
    int gid = lane >> 2, tid4 = lane & 3;
    int warpM = wid & 3, warpN = wid >> 2;
    long long rowBase = (long long)blockIdx.x * 64 + warpM * 16;
    int colBase = blockIdx.y * 128 + warpN * 64;

    long long r0 = rowBase + gid;
    long long r1 = r0 + 8;
    long long c0 = (r0 < NN) ? r0 : NN - 1;
    long long c1 = (r1 < NN) ? r1 : NN - 1;
    long long rp0 = c0 * 32, rp1 = c1 * 32;

    float acc[8][4];
#pragma unroll
    for (int nb = 0; nb < 8; nb++)
#pragma unroll
        for (int q = 0; q < 4; q++) acc[nb][q] = 0.f;

#pragma unroll
    for (int kc = 0; kc < 4; kc++) {
        uint2 u0 = *(const uint2*)(g_dzp + rp0 + kc * 8 + tid4 * 2);
        uint2 u1 = *(const uint2*)(g_dzp + rp1 + kc * 8 + tid4 * 2);
        unsigned a[4] = { u0.x, u1.x, u0.y, u1.y };
#pragma unroll
        for (int nb = 0; nb < 8; nb++) {
            int nbg = colBase / 8 + nb;
            uint2 b = *(const uint2*)(g_Wf2p + (kc * 128 + nbg) * 64 + lane * 2);
            mma16816h(acc[nb], a, b.x, b.y);
        }
    }

#pragma unroll
    for (int nb = 0; nb < 8; nb++) {
        int c = colBase + nb * 8 + tid4 * 2;
        float2 bv = *(const float2*)(bf2 + c);
        if (r0 < NN) {
            float2 o = make_float2(fmaxf(acc[nb][0] + bv.x, 0.f),
                                   fmaxf(acc[nb][1] + bv.y, 0.f));
            __stcs((float2*)(out + r0 * CIN + c), o);
        }
        if (r1 < NN) {
            float2 o = make_float2(fmaxf(acc[nb][2] + bv.x, 0.f),
                                   fmaxf(acc[nb][3] + bv.y, 0.f));
            __stcs((float2*)(out + r1 * CIN + c), o);
        }
    }
}

// ---------------------------------------------------------------------------
extern "C" void kernel_launch(void* const* d_in, const int* in_sizes, int n_in,
                              void* d_out, int out_size) {
    const float* x    = (const float*)d_in[0];
    const void*  ei   = d_in[1];
    const float* Wg1  = (const float*)d_in[2];
    const float* bg1  = (const float*)d_in[3];
    const float* Wg2  = (const float*)d_in[4];
    const float* bg2  = (const float*)d_in[5];
    const float* Wf1  = (const float*)d_in[6];
    const float* bf1  = (const float*)d_in[7];
    const float* Wf2  = (const float*)d_in[8];
    const float* bf2  = (const float*)d_in[9];
    float* out = (float*)d_out;

    histprep_kernel<<<HISTB + PACKB, 256>>>(ei, Wg1, Wf2, Wg2, Wf1);  // 1
    alloc_kernel<<<NBLK, 256>>>();                                     // 2
    gemmscat_kernel<<<GEMMB + HISTB, 256>>>(x, ei);                    // 3
    gather1_kernel<<<(NN + 7) / 8, 256>>>(bg1);                        // 4 <- profiled

    t2_mma_kernel<<<(NN + 127) / 128, 256>>>();                        // 5
    gather2_kernel<<<(NN + 7) / 8, 256>>>(bg2);                        // 6
    z_mma_kernel<<<(NN + 127) / 128, 256>>>(bf1);                      // 7

    dim3 g2((NN + 63) / 64, CIN / 128);
    decode2_mma_kernel<<<g2, 256>>>(bf2, out);                         // 8
}

// round 17
// speedup vs baseline: 1.6079x; 1.0318x over previous
#include <cuda_runtime.h>
#include <cuda_fp16.h>

#define NN   100000
#define EE   1600000
#define CIN  1024
#define HD   64
#define ZDIM 32

#define NBLK ((NN + 255) / 256)    // 391
#define HISTB (EE / 512)           // 3125 (2 edges/thread)
#define SCATB (EE / 256)           // 6250
#define PACKB 128                  // 32768 / 256
#define GEMMB ((NN + 127) / 128)   // 782

// ---------------- scratch (static __device__ — zero-initialized) ----------------
__device__ int   g_total;                 // reset by decode2 tail each run
__device__ int   g_deg[NN];               // re-zeroed by decode2 tail each run
__device__ int   g_off[NN];
__device__ int   g_cur[NN];
__device__ int   g_csr[EE];
__device__ float g_dinv[NN];
__device__ unsigned g_t1h[NN * 32 + 32];  // dinv-scaled x@Wg1, fp16 half2 (+zero pad row)
__device__ unsigned g_hh[NN * 32];        // encoder hidden h (post-relu), fp16 half2
__device__ unsigned g_t2h[NN * 16 + 16];  // dinv-scaled t2 = h@Wg2, fp16 half2 (+zero pad row)
__device__ unsigned g_zh[NN * 16];        // encoder output z, fp16 half2
__device__ unsigned g_dzp[NN * 32];       // decoder hidden, fp16 half2 words

// K-PERMUTED frag-packed weights (lane t owns phys k {4t..4t+3} per 16-chunk).
// Wf2 additionally N-PERMUTED: frag col c of block nb <- natural n = (nb>>1)*16 + 2c + (nb&1),
// so each thread's accumulators for an nb-pair form 4 consecutive natural columns.
__device__ __align__(16) unsigned g_Wg1p[64 * 8 * 64];     // 128 KB
__device__ __align__(16) unsigned g_Wf2p[4 * 128 * 64];    // 128 KB
__device__ __align__(16) unsigned g_Wg2p[4 * 4 * 64];      // 4 KB
__device__ __align__(16) unsigned g_Wf1p[2 * 8 * 64];      // 4 KB

// ---------------- helpers ----------------
__device__ __forceinline__ unsigned h2pack(float x0, float x1) {
    __half2 h = __float22half2_rn(make_float2(x0, x1));
    return *reinterpret_cast<unsigned*>(&h);
}
__device__ __forceinline__ float2 h2unpack(unsigned w) {
    return __half22float2(*reinterpret_cast<__half2*>(&w));
}
__device__ __forceinline__ unsigned hadd2u(unsigned a, unsigned b) {
    __half2 r = __hadd2(*reinterpret_cast<__half2*>(&a), *reinterpret_cast<__half2*>(&b));
    return *reinterpret_cast<unsigned*>(&r);
}

__device__ __forceinline__ void mma16816h(float* c, const unsigned* a, unsigned b0, unsigned b1) {
    asm volatile(
        "mma.sync.aligned.m16n8k16.row.col.f32.f16.f16.f32 "
        "{%0,%1,%2,%3}, {%4,%5,%6,%7}, {%8,%9}, {%0,%1,%2,%3};\n"
        : "+f"(c[0]), "+f"(c[1]), "+f"(c[2]), "+f"(c[3])
        : "r"(a[0]), "r"(a[1]), "r"(a[2]), "r"(a[3]), "r"(b0), "r"(b1));
}

__device__ __forceinline__ void cp16(unsigned smem_addr, const void* gptr) {
    asm volatile("cp.async.ca.shared.global [%0], [%1], 16;\n"
                 :: "r"(smem_addr), "l"(gptr));
}
__device__ __forceinline__ void cp_commit() { asm volatile("cp.async.commit_group;\n"); }
__device__ __forceinline__ void cp_wait1()  { asm volatile("cp.async.wait_group 1;\n" ::: "memory"); }

__device__ __forceinline__ int detect_is64_block(const int* ei32, int* s_flag) {
    if (threadIdx.x == 0) {
        int nz = 0;
#pragma unroll
        for (int k = 0; k < 16; k++) nz |= (ei32[2 * k + 1] != 0);
        *s_flag = nz ? 0 : 1;
    }
    __syncthreads();
    return *s_flag;
}

// K-permuted pack: frag j-pair (j=0,1) <- physical k = kc*16 + (lane&3)*4 + j*2
__device__ __forceinline__ void pack_one(const float* __restrict__ W, int K, int N,
                                         unsigned* __restrict__ pw, int idx) {
    int lane2 = idx & 63;
    int j = lane2 & 1;
    int lane = lane2 >> 1;
    int nb = (idx >> 6) % (N / 8);
    int kc = idx / (64 * (N / 8));
    int k0 = kc * 16 + (lane & 3) * 4 + j * 2;
    int n = nb * 8 + (lane >> 2);
    pw[idx] = h2pack(W[(long long)k0 * N + n], W[(long long)(k0 + 1) * N + n]);
}

// K-permuted + N-permuted pack (for Wf2 / decode2 float4 stores)
__device__ __forceinline__ void pack_one_nperm(const float* __restrict__ W, int K, int N,
                                               unsigned* __restrict__ pw, int idx) {
    int lane2 = idx & 63;
    int j = lane2 & 1;
    int lane = lane2 >> 1;
    int nb = (idx >> 6) % (N / 8);
    int kc = idx / (64 * (N / 8));
    int k0 = kc * 16 + (lane & 3) * 4 + j * 2;
    int c = lane >> 2;                               // frag col within block
    int n = (nb >> 1) * 16 + 2 * c + (nb & 1);       // natural column
    pw[idx] = h2pack(W[(long long)k0 * N + n], W[(long long)(k0 + 1) * N + n]);
}

// ---------------- launch 1: hist (2 edges/thread) + weight packing ----------------
__global__ void histprep_kernel(const void* __restrict__ ei,
                                const float* __restrict__ Wg1,
                                const float* __restrict__ Wf2,
                                const float* __restrict__ Wg2,
                                const float* __restrict__ Wf1) {
    __shared__ int s_is64;
    int b = blockIdx.x;
    if (b < HISTB) {
        int is64 = detect_is64_block((const int*)ei, &s_is64);
        int e = b * 512 + threadIdx.x * 2;
        int d0, d1;
        if (is64) {
            longlong2 v = *(const longlong2*)((const long long*)ei + EE + e);
            d0 = (int)v.x; d1 = (int)v.y;
        } else {
            int2 v = *(const int2*)((const int*)ei + EE + e);
            d0 = v.x; d1 = v.y;
        }
        atomicAdd(&g_deg[d0], 1);
        atomicAdd(&g_deg[d1], 1);
    } else {
        int idx = (b - HISTB) * 256 + threadIdx.x;   // 0..32767
        pack_one(Wg1, CIN, HD, g_Wg1p, idx);
        pack_one_nperm(Wf2, HD, CIN, g_Wf2p, idx);
        if (idx < 4 * 4 * 64) pack_one(Wg2, HD, ZDIM, g_Wg2p, idx);
        if (idx < 2 * 8 * 64) pack_one(Wf1, ZDIM, HD, g_Wf1p, idx);
    }
}

// ---------------- launch 2: alloc ----------------
__global__ void alloc_kernel() {
    int i = blockIdx.x * blockDim.x + threadIdx.x;
    int lane = threadIdx.x & 31;
    int d = (i < NN) ? g_deg[i] : 0;
    int p = d;
#pragma unroll
    for (int o = 1; o < 32; o <<= 1) {
        int t = __shfl_up_sync(0xffffffffu, p, o);
        if (lane >= o) p += t;
    }
    int tot = __shfl_sync(0xffffffffu, p, 31);
    int base = 0;
    if (lane == 31) base = atomicAdd(&g_total, tot);
    base = __shfl_sync(0xffffffffu, base, 31);
    if (i < NN) {
        int off = base + p - d;
        g_off[i] = off;
        g_cur[i] = off;
        g_dinv[i] = rsqrtf((float)(d + 1));
    }
}

// ---------------- launch 3: gemm1 + scatter (fused) ----------------
__global__ __launch_bounds__(256, 3) void gemmscat_kernel(const float* __restrict__ x,
                                                          const void* __restrict__ ei) {
    __shared__ __align__(16) unsigned Bs[3 * 512];
    __shared__ int s_is64;
    int tid = threadIdx.x;

    if (blockIdx.x >= GEMMB) {
        int is64 = detect_is64_block((const int*)ei, &s_is64);
        int e = (blockIdx.x - GEMMB) * 256 + tid;
        int s, d;
        if (is64) {
            s = (int)((const long long*)ei)[e];
            d = (int)((const long long*)ei)[EE + e];
        } else {
            s = ((const int*)ei)[e];
            d = ((const int*)ei)[EE + e];
        }
        int pos = atomicAdd(&g_cur[d], 1);
        g_csr[pos] = s;
        return;
    }

    int wid = tid >> 5, lane = tid & 31;
    int gid = lane >> 2, tid4 = lane & 3;
    long long rowBase = (long long)blockIdx.x * 128 + wid * 16;

    long long r0 = rowBase + gid;
    long long r1 = r0 + 8;
    long long c0 = (r0 < NN) ? r0 : NN - 1;
    long long c1 = (r1 < NN) ? r1 : NN - 1;
    const float* p0 = x + c0 * CIN;
    const float* p1 = x + c1 * CIN;

    unsigned sbase = (unsigned)__cvta_generic_to_shared(Bs);
    int doCp = (tid < 128);

    if (doCp) cp16(sbase + tid * 16, g_Wg1p + tid * 4);
    cp_commit();
    if (doCp) cp16(sbase + 512 * 4 + tid * 16, g_Wg1p + 512 + tid * 4);
    cp_commit();

    float acc[8][4];
#pragma unroll
    for (int nb = 0; nb < 8; nb++)
#pragma unroll
        for (int q = 0; q < 4; q++) acc[nb][q] = 0.f;

    float4 a0, a1;
    {
        int col = tid4 * 4;
        a0 = __ldcs((const float4*)(p0 + col));
        a1 = __ldcs((const float4*)(p1 + col));
    }

    for (int kc = 0; kc < 64; kc++) {
        float4 n0, n1;
        if (kc < 63) {
            int col = (kc + 1) * 16 + tid4 * 4;
            n0 = __ldcs((const float4*)(p0 + col));
            n1 = __ldcs((const float4*)(p1 + col));
        }

        cp_wait1();
        __syncthreads();
        if (kc + 2 < 64 && doCp)
            cp16(sbase + ((kc + 2) % 3) * 512 * 4 + tid * 16, g_Wg1p + (kc + 2) * 512 + tid * 4);
        cp_commit();

        unsigned at[4];
        at[0] = h2pack(a0.x, a0.y);
        at[1] = h2pack(a1.x, a1.y);
        at[2] = h2pack(a0.z, a0.w);
        at[3] = h2pack(a1.z, a1.w);

        const unsigned* BsS = Bs + (kc % 3) * 512;
#pragma unroll
        for (int nb = 0; nb < 8; nb++) {
            uint2 b = *(const uint2*)(BsS + nb * 64 + lane * 2);
            mma16816h(acc[nb], at, b.x, b.y);
        }
        a0 = n0; a1 = n1;
    }

    float di0 = (r0 < NN) ? g_dinv[r0] : 0.f;
    float di1 = (r1 < NN) ? g_dinv[r1] : 0.f;
#pragma unroll
    for (int nb = 0; nb < 8; nb++) {
        int w = nb * 4 + tid4;
        if (r0 < NN) g_t1h[r0 * 32 + w] = h2pack(acc[nb][0] * di0, acc[nb][1] * di0);
        if (r1 < NN) g_t1h[r1 * 32 + w] = h2pack(acc[nb][2] * di1, acc[nb][3] * di1);
    }
}

// ------- launch 4 (profiled): gather1 — HADD2 aggregation + relu -------
__global__ __launch_bounds__(256) void gather1_kernel(const float* __restrict__ bg1) {
    __shared__ float bg1s[HD];
    int tid = threadIdx.x;
    if (tid < HD) bg1s[tid] = bg1[tid];
    __syncthreads();

    int v = blockIdx.x * 8 + (tid >> 5);
    if (v >= NN) return;
    int lane = tid & 31;

    float a0 = 0.f, a1 = 0.f;
    int beg = g_off[v];
    int cnt = g_deg[v];
    for (int base = 0; base < cnt; base += 32) {
        int j = base + lane;
        int soff = (j < cnt) ? g_csr[beg + j] * 32 : NN * 32;
        int rem = cnt - base;
        if (rem > 32) rem = 32;
#pragma unroll
        for (int qq = 0; qq < 4; qq++) {
            if (qq * 8 >= rem) break;
            unsigned hA = 0, hB = 0;
#pragma unroll
            for (int qi = 0; qi < 8; qi++) {
                int ov = __shfl_sync(0xffffffffu, soff, qq * 8 + qi);
                unsigned fv = g_t1h[ov + lane];
                if (qi & 1) hB = hadd2u(hB, fv);
                else        hA = hadd2u(hA, fv);
            }
            float2 fA = h2unpack(hA);
            float2 fB = h2unpack(hB);
            a0 += fA.x + fB.x;
            a1 += fA.y + fB.y;
        }
    }
    float di = g_dinv[v];
    float2 pv = h2unpack(g_t1h[(long long)v * 32 + lane]);
    float h0 = fmaxf(di * (a0 + pv.x) + bg1s[2 * lane],     0.f);
    float h1 = fmaxf(di * (a1 + pv.y) + bg1s[2 * lane + 1], 0.f);
    g_hh[(long long)v * 32 + lane] = h2pack(h0, h1);
}

// ---- launch 5: t2 MMA — t2h = dinv .* (h[N,64] @ Wg2[64,32]) ----
__global__ __launch_bounds__(256, 3) void t2_mma_kernel() {
    int tid = threadIdx.x;
    int wid = tid >> 5, lane = tid & 31;
    int gid = lane >> 2, tid4 = lane & 3;
    long long rowBase = (long long)blockIdx.x * 128 + wid * 16;

    long long r0 = rowBase + gid;
    long long r1 = r0 + 8;
    long long c0 = (r0 < NN) ? r0 : NN - 1;
    long long c1 = (r1 < NN) ? r1 : NN - 1;
    long long rp0 = c0 * 32, rp1 = c1 * 32;

    float acc[4][4];
#pragma unroll
    for (int nb = 0; nb < 4; nb++)
#pragma unroll
        for (int q = 0; q < 4; q++) acc[nb][q] = 0.f;

#pragma unroll
    for (int kc = 0; kc < 4; kc++) {
        uint2 u0 = *(const uint2*)(g_hh + rp0 + kc * 8 + tid4 * 2);
        uint2 u1 = *(const uint2*)(g_hh + rp1 + kc * 8 + tid4 * 2);
        unsigned a[4] = { u0.x, u1.x, u0.y, u1.y };
#pragma unroll
        for (int nb = 0; nb < 4; nb++) {
            uint2 b = *(const uint2*)(g_Wg2p + (kc * 4 + nb) * 64 + lane * 2);
            mma16816h(acc[nb], a, b.x, b.y);
        }
    }

    float di0 = (r0 < NN) ? g_dinv[r0] : 0.f;
    float di1 = (r1 < NN) ? g_dinv[r1] : 0.f;
#pragma unroll
    for (int nb = 0; nb < 4; nb++) {
        int w = nb * 4 + tid4;
        if (r0 < NN) g_t2h[r0 * 16 + w] = h2pack(acc[nb][0] * di0, acc[nb][1] * di0);
        if (r1 < NN) g_t2h[r1 * 16 + w] = h2pack(acc[nb][2] * di1, acc[nb][3] * di1);
    }
}

// -- launch 6: gather2 — half-warp-split HADD2 aggregation (no redundant work) --
__global__ __launch_bounds__(256) void gather2_kernel(const float* __restrict__ bg2) {
    __shared__ float bg2s[ZDIM];
    int tid = threadIdx.x;
    if (tid < ZDIM) bg2s[tid] = bg2[tid];
    __syncthreads();

    int v = blockIdx.x * 8 + (tid >> 5);
    if (v >= NN) return;
    int lane = tid & 31;
    int lp = lane & 15;
    int half = lane >> 4;
    unsigned hmask = half ? 0xFFFF0000u : 0x0000FFFFu;
    int qb = half * 16;

    float a0 = 0.f, a1 = 0.f;
    int beg = g_off[v];
    int cnt = g_deg[v];
    for (int base = 0; base < cnt; base += 32) {
        int j = base + lane;
        int soff = (j < cnt) ? g_csr[beg + j] * 16 : NN * 16;
        int rem = cnt - base;
        if (rem > 32) rem = 32;
        // each half-warp processes its own 16 neighbors (disjoint masks; halves
        // may diverge in trip count — shuffles stay within the converged half)
#pragma unroll
        for (int qq = 0; qq < 2; qq++) {
            if (qb + qq * 8 >= rem) break;
            unsigned hA = 0, hB = 0;
#pragma unroll
            for (int qi = 0; qi < 8; qi++) {
                int ov = __shfl_sync(hmask, soff, qb + qq * 8 + qi);
                unsigned fv = g_t2h[ov + lp];
                if (qi & 1) hB = hadd2u(hB, fv);
                else        hA = hadd2u(hA, fv);
            }
            float2 fA = h2unpack(hA);
            float2 fB = h2unpack(hB);
            a0 += fA.x + fB.x;
            a1 += fA.y + fB.y;
        }
    }
    // combine the two half-warp partial sums
    a0 += __shfl_xor_sync(0xffffffffu, a0, 16);
    a1 += __shfl_xor_sync(0xffffffffu, a1, 16);

    float di = g_dinv[v];
    float2 pv = h2unpack(g_t2h[(long long)v * 16 + lp]);
    float z0 = di * (a0 + pv.x) + bg2s[2 * lp];
    float z1 = di * (a1 + pv.y) + bg2s[2 * lp + 1];
    if (lane < 16)
        g_zh[(long long)v * 16 + lp] = h2pack(z0, z1);
}

// ---- launch 7: z MMA — dzp = relu(z[N,32] @ Wf1[32,64] + bf1) ----
__global__ __launch_bounds__(256, 3) void z_mma_kernel(const float* __restrict__ bf1) {
    __shared__ float bf1s[HD];
    int tid = threadIdx.x;
    if (tid < HD) bf1s[tid] = bf1[tid];
    __syncthreads();

    int wid = tid >> 5, lane = tid & 31;
    int gid = lane >> 2, tid4 = lane & 3;
    long long rowBase = (long long)blockIdx.x * 128 + wid * 16;

    long long r0 = rowBase + gid;
    long long r1 = r0 + 8;
    long long c0 = (r0 < NN) ? r0 : NN - 1;
    long long c1 = (r1 < NN) ? r1 : NN - 1;
    long long rp0 = c0 * 16, rp1 = c1 * 16;

    float acc[8][4];
#pragma unroll
    for (int nb = 0; nb < 8; nb++)
#pragma unroll
        for (int q = 0; q < 4; q++) acc[nb][q] = 0.f;

#pragma unroll
    for (int kc = 0; kc < 2; kc++) {
        uint2 u0 = *(const uint2*)(g_zh + rp0 + kc * 8 + tid4 * 2);
        uint2 u1 = *(const uint2*)(g_zh + rp1 + kc * 8 + tid4 * 2);
        unsigned a[4] = { u0.x, u1.x, u0.y, u1.y };
#pragma unroll
        for (int nb = 0; nb < 8; nb++) {
            uint2 b = *(const uint2*)(g_Wf1p + (kc * 8 + nb) * 64 + lane * 2);
            mma16816h(acc[nb], a, b.x, b.y);
        }
    }

#pragma unroll
    for (int nb = 0; nb < 8; nb++) {
        int c = nb * 8 + tid4 * 2;
        float b0 = bf1s[c], b1 = bf1s[c + 1];
        int w = nb * 4 + tid4;
        if (r0 < NN)
            g_dzp[r0 * 32 + w] = h2pack(fmaxf(acc[nb][0] + b0, 0.f), fmaxf(acc[nb][1] + b1, 0.f));
        if (r1 < NN)
            g_dzp[r1 * 32 + w] = h2pack(fmaxf(acc[nb][2] + b0, 0.f), fmaxf(acc[nb][3] + b1, 0.f));
    }
}

// ---- launch 8: decode2 (N-permuted Wf2 -> float4 stores) + tail cleanup ----
__global__ __launch_bounds__(256, 3) void decode2_mma_kernel(const float* __restrict__ bf2,
                                                             float* __restrict__ out) {
    int tid = threadIdx.x;

    if (blockIdx.y == 0) {
        int i = blockIdx.x * 256 + tid;
        if (i < NN) g_deg[i] = 0;
        if (i == 0) g_total = 0;
    }

    int wid = tid >> 5, lane = tid & 31;
    int gid = lane >> 2, tid4 = lane & 3;
    int warpM = wid & 3, warpN = wid >> 2;
    long long rowBase = (long long)blockIdx.x * 64 + warpM * 16;
    int colBase = blockIdx.y * 128 + warpN * 64;

    long long r0 = rowBase + gid;
    long long r1 = r0 + 8;
    long long c0 = (r0 < NN) ? r0 : NN - 1;
    long long c1 = (r1 < NN) ? r1 : NN - 1;
    long long rp0 = c0 * 32, rp1 = c1 * 32;

    float acc[8][4];
#pragma unroll
    for (int nb = 0; nb < 8; nb++)
#pragma unroll
        for (int q = 0; q < 4; q++) acc[nb][q] = 0.f;

#pragma unroll
    for (int kc = 0; kc < 4; kc++) {
        uint2 u0 = *(const uint2*)(g_dzp + rp0 + kc * 8 + tid4 * 2);
        uint2 u1 = *(const uint2*)(g_dzp + rp1 + kc * 8 + tid4 * 2);
        unsigned a[4] = { u0.x, u1.x, u0.y, u1.y };
#pragma unroll
        for (int nb = 0; nb < 8; nb++) {
            int nbg = colBase / 8 + nb;
            uint2 b = *(const uint2*)(g_Wf2p + (kc * 128 + nbg) * 64 + lane * 2);
            mma16816h(acc[nb], a, b.x, b.y);
        }
    }

    // N-permuted epilogue: nb pair (2m, 2m+1) -> natural cols colBase + m*16 + tid4*4 ..+3
#pragma unroll
    for (int m = 0; m < 4; m++) {
        int c = colBase + m * 16 + tid4 * 4;
        float4 bv = *(const float4*)(bf2 + c);
        if (r0 < NN) {
            float4 o;
            o.x = fmaxf(acc[2 * m][0]     + bv.x, 0.f);
            o.y = fmaxf(acc[2 * m + 1][0] + bv.y, 0.f);
            o.z = fmaxf(acc[2 * m][1]     + bv.z, 0.f);
            o.w = fmaxf(acc[2 * m + 1][1] + bv.w, 0.f);
            __stcs((float4*)(out + r0 * CIN + c), o);
        }
        if (r1 < NN) {
            float4 o;
            o.x = fmaxf(acc[2 * m][2]     + bv.x, 0.f);
            o.y = fmaxf(acc[2 * m + 1][2] + bv.y, 0.f);
            o.z = fmaxf(acc[2 * m][3]     + bv.z, 0.f);
            o.w = fmaxf(acc[2 * m + 1][3] + bv.w, 0.f);
            __stcs((float4*)(out + r1 * CIN + c), o);
        }
    }
}

// ---------------------------------------------------------------------------
extern "C" void kernel_launch(void* const* d_in, const int* in_sizes, int n_in,
                              void* d_out, int out_size) {
    const float* x    = (const float*)d_in[0];
    const void*  ei   = d_in[1];
    const float* Wg1  = (const float*)d_in[2];
    const float* bg1  = (const float*)d_in[3];
    const float* Wg2  = (const float*)d_in[4];
    const float* bg2  = (const float*)d_in[5];
    const float* Wf1  = (const float*)d_in[6];
    const float* bf1  = (const float*)d_in[7];
    const float* Wf2  = (const float*)d_in[8];
    const float* bf2  = (const float*)d_in[9];
    float* out = (float*)d_out;

    histprep_kernel<<<HISTB + PACKB, 256>>>(ei, Wg1, Wf2, Wg2, Wf1);  // 1
    alloc_kernel<<<NBLK, 256>>>();                                     // 2
    gemmscat_kernel<<<GEMMB + SCATB, 256>>>(x, ei);                    // 3
    gather1_kernel<<<(NN + 7) / 8, 256>>>(bg1);                        // 4 <- profiled

    t2_mma_kernel<<<(NN + 127) / 128, 256>>>();                        // 5
    gather2_kernel<<<(NN + 7) / 8, 256>>>(bg2);                        // 6
    z_mma_kernel<<<(NN + 127) / 128, 256>>>(bf1);                      // 7

    dim3 g2((NN + 63) / 64, CIN / 128);
    decode2_mma_kernel<<<g2, 256>>>(bf2, out);                         // 8
}